// round 1
// baseline (speedup 1.0000x reference)
#include <cuda_runtime.h>
#include <cuda_bf16.h>

#define MAXN 100000
#define MAXE 1600000
#define DIMV 128
#define SCAN_B 1024

// ---------------- scratch (device globals; no allocation allowed) -------------
__device__ float g_h [MAXN * DIMV];
__device__ float g_hw[MAXN * DIMV];
__device__ int   g_csr[MAXE];
__device__ int   g_row_ptr[MAXN + 1];
__device__ int   g_cursor[MAXN];
__device__ int   g_cnt_src[MAXN];
__device__ int   g_cnt_dst[MAXN];
__device__ float g_norm_src[MAXN];
__device__ float g_norm_dst[MAXN];
__device__ int   g_spine[256];

// ---------------- small helpers ----------------------------------------------
__device__ __forceinline__ float4 f4add(float4 a, float4 b) {
    return make_float4(a.x + b.x, a.y + b.y, a.z + b.z, a.w + b.w);
}

// ---------------- zero counters ----------------------------------------------
__global__ void k_zero_counts(int n) {
    int i = blockIdx.x * blockDim.x + threadIdx.x;
    if (i < n) { g_cnt_src[i] = 0; g_cnt_dst[i] = 0; }
}

__global__ void k_zero_out(float* out, int n) {
    int i = blockIdx.x * blockDim.x + threadIdx.x;
    if (i < n) out[i] = 0.0f;
}

// ---------------- degree histograms ------------------------------------------
__global__ void k_hist(const int* __restrict__ src, const int* __restrict__ dst, int E) {
    int e = blockIdx.x * blockDim.x + threadIdx.x;
    if (e < E) {
        atomicAdd(&g_cnt_src[src[e]], 1);
        atomicAdd(&g_cnt_dst[dst[e]], 1);
    }
}

__global__ void k_norms(int n) {
    int i = blockIdx.x * blockDim.x + threadIdx.x;
    if (i < n) {
        g_norm_src[i] = rsqrtf((float)max(g_cnt_src[i], 1));
        g_norm_dst[i] = rsqrtf((float)max(g_cnt_dst[i], 1));
    }
}

// ---------------- exclusive scan of in-degree counts -> row_ptr ---------------
__global__ void k_scan1(int n) {
    __shared__ int s[SCAN_B];
    int i = blockIdx.x * SCAN_B + threadIdx.x;
    int v = (i < n) ? g_cnt_dst[i] : 0;
    s[threadIdx.x] = v;
    __syncthreads();
    for (int off = 1; off < SCAN_B; off <<= 1) {
        int t = (threadIdx.x >= off) ? s[threadIdx.x - off] : 0;
        __syncthreads();
        s[threadIdx.x] += t;
        __syncthreads();
    }
    if (i < n) g_row_ptr[i] = s[threadIdx.x] - v;   // exclusive within block
    if (threadIdx.x == SCAN_B - 1) g_spine[blockIdx.x] = s[SCAN_B - 1];
}

__global__ void k_scan2(int nb) {
    __shared__ int s[SCAN_B];
    int v = (threadIdx.x < nb) ? g_spine[threadIdx.x] : 0;
    s[threadIdx.x] = v;
    __syncthreads();
    for (int off = 1; off < SCAN_B; off <<= 1) {
        int t = (threadIdx.x >= off) ? s[threadIdx.x - off] : 0;
        __syncthreads();
        s[threadIdx.x] += t;
        __syncthreads();
    }
    if (threadIdx.x < nb) g_spine[threadIdx.x] = s[threadIdx.x] - v; // exclusive
}

__global__ void k_scan3(int n, int E) {
    int i = blockIdx.x * blockDim.x + threadIdx.x;
    if (i < n) {
        int r = g_row_ptr[i] + g_spine[i / SCAN_B];
        g_row_ptr[i] = r;
        g_cursor[i]  = r;
    }
    if (i == 0) g_row_ptr[n] = E;
}

// ---------------- CSR fill (counting sort of edges by dst) -------------------
__global__ void k_fill(const int* __restrict__ src, const int* __restrict__ dst, int E) {
    int e = blockIdx.x * blockDim.x + threadIdx.x;
    if (e < E) {
        int pos = atomicAdd(&g_cursor[dst[e]], 1);
        g_csr[pos] = src[e];
    }
}

// ---------------- embedding gather -------------------------------------------
__global__ void k_embed(const int* __restrict__ feat_id, const float* __restrict__ emb, int n) {
    int idx = blockIdx.x * blockDim.x + threadIdx.x;   // over n*32 float4s
    if (idx < n * 32) {
        int node = idx >> 5;
        int c    = idx & 31;
        reinterpret_cast<float4*>(g_h)[idx] =
            reinterpret_cast<const float4*>(emb)[feat_id[node] * 32 + c];
    }
}

// ---------------- GEMM: hw = norm_src ⊙ (h @ W) ------------------------------
// block: 256 threads, 64 rows; W (64KB) + 64 h-rows (32KB) in dynamic smem.
// warp handles 8 rows, each lane 4 output columns.
__global__ void __launch_bounds__(256) k_gemm(const float* __restrict__ W, int n) {
    extern __shared__ float smem[];
    float* Ws = smem;                 // 128*128
    float* hs = smem + DIMV * DIMV;   // 64*128
    int tid = threadIdx.x;

    // load W
    for (int i = tid; i < DIMV * DIMV / 4; i += 256)
        reinterpret_cast<float4*>(Ws)[i] = reinterpret_cast<const float4*>(W)[i];

    int row0 = blockIdx.x * 64;
    // load 64 rows of h
    for (int i = tid; i < 64 * 32; i += 256) {
        int r = i >> 5, c = i & 31;
        int gr = row0 + r;
        reinterpret_cast<float4*>(hs)[i] =
            (gr < n) ? reinterpret_cast<const float4*>(g_h)[gr * 32 + c]
                     : make_float4(0.f, 0.f, 0.f, 0.f);
    }
    __syncthreads();

    int warp = tid >> 5, lane = tid & 31;
    const float* hb = hs + (warp * 8) * DIMV;

    float4 acc[8];
#pragma unroll
    for (int r = 0; r < 8; r++) acc[r] = make_float4(0.f, 0.f, 0.f, 0.f);

#pragma unroll 8
    for (int k = 0; k < DIMV; k++) {
        float4 w = reinterpret_cast<const float4*>(Ws)[k * 32 + lane];
#pragma unroll
        for (int r = 0; r < 8; r++) {
            float a = hb[r * DIMV + k];
            acc[r].x = fmaf(a, w.x, acc[r].x);
            acc[r].y = fmaf(a, w.y, acc[r].y);
            acc[r].z = fmaf(a, w.z, acc[r].z);
            acc[r].w = fmaf(a, w.w, acc[r].w);
        }
    }

#pragma unroll
    for (int r = 0; r < 8; r++) {
        int gr = row0 + warp * 8 + r;
        if (gr < n) {
            float ns = g_norm_src[gr];
            float4 o = make_float4(acc[r].x * ns, acc[r].y * ns, acc[r].z * ns, acc[r].w * ns);
            reinterpret_cast<float4*>(g_hw)[gr * 32 + lane] = o;
        }
    }
}

// ---------------- edge aggregation: h = relu(norm_dst ⊙ (A @ hw) + b) --------
// warp per dst node; lane owns 4 dims (float4). CSR traversal, unroll 4.
__global__ void __launch_bounds__(256) k_agg(const float* __restrict__ bias, int n) {
    int warp = (blockIdx.x * blockDim.x + threadIdx.x) >> 5;
    int lane = threadIdx.x & 31;
    if (warp >= n) return;

    int beg = g_row_ptr[warp];
    int end = g_row_ptr[warp + 1];

    const float4* hw4 = reinterpret_cast<const float4*>(g_hw);
    float4 a0 = make_float4(0.f, 0.f, 0.f, 0.f), a1 = a0, a2 = a0, a3 = a0;

    int e = beg;
    for (; e + 3 < end; e += 4) {
        int s0 = g_csr[e], s1 = g_csr[e + 1], s2 = g_csr[e + 2], s3 = g_csr[e + 3];
        a0 = f4add(a0, hw4[s0 * 32 + lane]);
        a1 = f4add(a1, hw4[s1 * 32 + lane]);
        a2 = f4add(a2, hw4[s2 * 32 + lane]);
        a3 = f4add(a3, hw4[s3 * 32 + lane]);
    }
    for (; e < end; ++e)
        a0 = f4add(a0, hw4[g_csr[e] * 32 + lane]);

    float4 a = f4add(f4add(a0, a1), f4add(a2, a3));
    float nd = g_norm_dst[warp];
    float4 bb = reinterpret_cast<const float4*>(bias)[lane];
    float4 o;
    o.x = fmaxf(fmaf(a.x, nd, bb.x), 0.f);
    o.y = fmaxf(fmaf(a.y, nd, bb.y), 0.f);
    o.z = fmaxf(fmaf(a.z, nd, bb.z), 0.f);
    o.w = fmaxf(fmaf(a.w, nd, bb.w), 0.f);
    reinterpret_cast<float4*>(g_h)[warp * 32 + lane] = o;
}

// ---------------- per-graph max readout (graph_ids sorted) -------------------
// block: 128 threads (one per dim), scans 512 consecutive nodes with running max,
// flushing via atomicMax-as-int on graph boundaries (h >= 0 post-relu).
__global__ void k_readout(const int* __restrict__ gids, float* __restrict__ out, int n) {
    __shared__ int sg[512];
    int n0 = blockIdx.x * 512;
    int cnt = min(512, n - n0);
    if (cnt <= 0) return;
    for (int i = threadIdx.x; i < cnt; i += 128) sg[i] = gids[n0 + i];
    __syncthreads();

    int d = threadIdx.x;
    int cur = sg[0];
    float m = 0.f;
    for (int i = 0; i < cnt; i++) {
        int g = sg[i];
        if (g != cur) {
            atomicMax(reinterpret_cast<int*>(&out[cur * DIMV + d]), __float_as_int(m));
            m = 0.f;
            cur = g;
        }
        m = fmaxf(m, g_h[(n0 + i) * DIMV + d]);
    }
    atomicMax(reinterpret_cast<int*>(&out[cur * DIMV + d]), __float_as_int(m));
}

// ---------------- launch ------------------------------------------------------
extern "C" void kernel_launch(void* const* d_in, const int* in_sizes, int n_in,
                              void* d_out, int out_size) {
    const int*   feat_id = (const int*)  d_in[0];
    const int*   src     = (const int*)  d_in[1];
    const int*   dst     = (const int*)  d_in[2];
    const int*   gids    = (const int*)  d_in[3];
    const float* emb     = (const float*)d_in[4];
    const float* W       = (const float*)d_in[5];
    const float* b       = (const float*)d_in[6];
    float*       out     = (float*)d_out;

    int N = in_sizes[0];
    int E = in_sizes[1];
    int LAYERS = in_sizes[6] / DIMV;

    const int T = 256;
    int nbN  = (N + T - 1) / T;
    int nbE  = (E + T - 1) / T;
    int nbSc = (N + SCAN_B - 1) / SCAN_B;

    // build degrees / norms / CSR
    k_zero_counts<<<nbN, T>>>(N);
    k_hist<<<nbE, T>>>(src, dst, E);
    k_norms<<<nbN, T>>>(N);
    k_scan1<<<nbSc, SCAN_B>>>(N);
    k_scan2<<<1, SCAN_B>>>(nbSc);
    k_scan3<<<nbN, T>>>(N, E);
    k_fill<<<nbE, T>>>(src, dst, E);

    // embedding
    int embThreads = N * 32;
    k_embed<<<(embThreads + T - 1) / T, T>>>(feat_id, emb, N);

    // GEMM smem opt-in (96KB dynamic)
    size_t gemm_smem = (size_t)(DIMV * DIMV + 64 * DIMV) * sizeof(float);
    cudaFuncSetAttribute(k_gemm, cudaFuncAttributeMaxDynamicSharedMemorySize,
                         (int)gemm_smem);

    int gemmBlocks = (N + 63) / 64;
    int aggBlocks  = (N + 7) / 8;   // 8 warps/block, warp per node

    for (int l = 0; l < LAYERS; l++) {
        k_gemm<<<gemmBlocks, 256, gemm_smem>>>(W + (size_t)l * DIMV * DIMV, N);
        k_agg<<<aggBlocks, 256>>>(b + (size_t)l * DIMV, N);
    }

    // readout
    k_zero_out<<<(out_size + T - 1) / T, T>>>(out, out_size);
    k_readout<<<(N + 511) / 512, 128>>>(gids, out, N);
}

// round 2
// speedup vs baseline: 1.0734x; 1.0734x over previous
#include <cuda_runtime.h>
#include <cuda_bf16.h>

#define MAXN 100000
#define MAXE 1600000
#define DIMV 128
#define SCAN_B 1024

// ---------------- scratch (device globals; no allocation allowed) -------------
__device__ float g_h [MAXN * DIMV];
__device__ float g_hw[MAXN * DIMV];
__device__ int   g_csr[MAXE];
__device__ int   g_row_ptr[MAXN + 1];
__device__ int   g_cursor[MAXN];
__device__ int   g_cnt_src[MAXN];
__device__ int   g_cnt_dst[MAXN];
__device__ float g_norm_src[MAXN];
__device__ float g_norm_dst[MAXN];
__device__ int   g_spine[256];

// ---------------- packed f32x2 helpers (Blackwell) ----------------------------
__device__ __forceinline__ unsigned long long pack2(float x, float y) {
    unsigned long long r;
    asm("mov.b64 %0, {%1, %2};" : "=l"(r) : "f"(x), "f"(y));
    return r;
}
__device__ __forceinline__ void unpack2(unsigned long long v, float& x, float& y) {
    asm("mov.b64 {%0, %1}, %2;" : "=f"(x), "=f"(y) : "l"(v));
}
__device__ __forceinline__ void fma2(unsigned long long& d,
                                     unsigned long long a, unsigned long long b) {
    asm("fma.rn.f32x2 %0, %1, %2, %0;" : "+l"(d) : "l"(a), "l"(b));
}

__device__ __forceinline__ float4 f4add(float4 a, float4 b) {
    return make_float4(a.x + b.x, a.y + b.y, a.z + b.z, a.w + b.w);
}

// ---------------- zero counters ----------------------------------------------
__global__ void k_zero_counts(int n) {
    int i = blockIdx.x * blockDim.x + threadIdx.x;
    if (i < n) { g_cnt_src[i] = 0; g_cnt_dst[i] = 0; }
}

__global__ void k_zero_out(float* out, int n) {
    int i = blockIdx.x * blockDim.x + threadIdx.x;
    if (i < n) out[i] = 0.0f;
}

// ---------------- degree histograms ------------------------------------------
__global__ void k_hist(const int* __restrict__ src, const int* __restrict__ dst, int E) {
    int e = blockIdx.x * blockDim.x + threadIdx.x;
    if (e < E) {
        atomicAdd(&g_cnt_src[src[e]], 1);
        atomicAdd(&g_cnt_dst[dst[e]], 1);
    }
}

__global__ void k_norms(int n) {
    int i = blockIdx.x * blockDim.x + threadIdx.x;
    if (i < n) {
        g_norm_src[i] = rsqrtf((float)max(g_cnt_src[i], 1));
        g_norm_dst[i] = rsqrtf((float)max(g_cnt_dst[i], 1));
    }
}

// ---------------- exclusive scan of in-degree counts -> row_ptr ---------------
__global__ void k_scan1(int n) {
    __shared__ int s[SCAN_B];
    int i = blockIdx.x * SCAN_B + threadIdx.x;
    int v = (i < n) ? g_cnt_dst[i] : 0;
    s[threadIdx.x] = v;
    __syncthreads();
    for (int off = 1; off < SCAN_B; off <<= 1) {
        int t = (threadIdx.x >= off) ? s[threadIdx.x - off] : 0;
        __syncthreads();
        s[threadIdx.x] += t;
        __syncthreads();
    }
    if (i < n) g_row_ptr[i] = s[threadIdx.x] - v;   // exclusive within block
    if (threadIdx.x == SCAN_B - 1) g_spine[blockIdx.x] = s[SCAN_B - 1];
}

__global__ void k_scan2(int nb) {
    __shared__ int s[SCAN_B];
    int v = (threadIdx.x < nb) ? g_spine[threadIdx.x] : 0;
    s[threadIdx.x] = v;
    __syncthreads();
    for (int off = 1; off < SCAN_B; off <<= 1) {
        int t = (threadIdx.x >= off) ? s[threadIdx.x - off] : 0;
        __syncthreads();
        s[threadIdx.x] += t;
        __syncthreads();
    }
    if (threadIdx.x < nb) g_spine[threadIdx.x] = s[threadIdx.x] - v; // exclusive
}

__global__ void k_scan3(int n, int E) {
    int i = blockIdx.x * blockDim.x + threadIdx.x;
    if (i < n) {
        int r = g_row_ptr[i] + g_spine[i / SCAN_B];
        g_row_ptr[i] = r;
        g_cursor[i]  = r;
    }
    if (i == 0) g_row_ptr[n] = E;
}

// ---------------- CSR fill (counting sort of edges by dst) -------------------
__global__ void k_fill(const int* __restrict__ src, const int* __restrict__ dst, int E) {
    int e = blockIdx.x * blockDim.x + threadIdx.x;
    if (e < E) {
        int pos = atomicAdd(&g_cursor[dst[e]], 1);
        g_csr[pos] = src[e];
    }
}

// ---------------- embedding gather -------------------------------------------
__global__ void k_embed(const int* __restrict__ feat_id, const float* __restrict__ emb, int n) {
    int idx = blockIdx.x * blockDim.x + threadIdx.x;   // over n*32 float4s
    if (idx < n * 32) {
        int node = idx >> 5;
        int c    = idx & 31;
        reinterpret_cast<float4*>(g_h)[idx] =
            reinterpret_cast<const float4*>(emb)[feat_id[node] * 32 + c];
    }
}

// ---------------- GEMM: hw = norm_src ⊙ (h @ W) ------------------------------
// block: 256 threads, 64 rows; W (64KB) + 64 h-rows (32KB) in dynamic smem.
// warp handles 8 rows; lane owns 4 output cols as two packed f32x2 accumulators.
// `a` operands are warp-broadcast LDS.128 (1 wavefront each) -> FMA-pipe bound.
__global__ void __launch_bounds__(256) k_gemm(const float* __restrict__ W, int n) {
    extern __shared__ float smem[];
    float* Ws = smem;                 // 128*128
    float* hs = smem + DIMV * DIMV;   // 64*128
    int tid = threadIdx.x;

    // load W
    for (int i = tid; i < DIMV * DIMV / 4; i += 256)
        reinterpret_cast<float4*>(Ws)[i] = reinterpret_cast<const float4*>(W)[i];

    int row0 = blockIdx.x * 64;
    // load 64 rows of h
    for (int i = tid; i < 64 * 32; i += 256) {
        int r = i >> 5, c = i & 31;
        int gr = row0 + r;
        reinterpret_cast<float4*>(hs)[i] =
            (gr < n) ? reinterpret_cast<const float4*>(g_h)[gr * 32 + c]
                     : make_float4(0.f, 0.f, 0.f, 0.f);
    }
    __syncthreads();

    int warp = tid >> 5, lane = tid & 31;
    const float4* hb4 = reinterpret_cast<const float4*>(hs + (warp * 8) * DIMV);
    const float4* Ws4 = reinterpret_cast<const float4*>(Ws);

    unsigned long long acc01[8], acc23[8];
#pragma unroll
    for (int r = 0; r < 8; r++) { acc01[r] = 0ull; acc23[r] = 0ull; }

    for (int k0 = 0; k0 < DIMV; k0 += 4) {
        float4 av[8];
#pragma unroll
        for (int r = 0; r < 8; r++)
            av[r] = hb4[r * 32 + (k0 >> 2)];        // broadcast across warp

#pragma unroll
        for (int kk = 0; kk < 4; kk++) {
            float4 w = Ws4[(k0 + kk) * 32 + lane];
            unsigned long long w01 = pack2(w.x, w.y);
            unsigned long long w23 = pack2(w.z, w.w);
#pragma unroll
            for (int r = 0; r < 8; r++) {
                float a = reinterpret_cast<const float*>(&av[r])[kk];
                unsigned long long aa = pack2(a, a);
                fma2(acc01[r], aa, w01);
                fma2(acc23[r], aa, w23);
            }
        }
    }

#pragma unroll
    for (int r = 0; r < 8; r++) {
        int gr = row0 + warp * 8 + r;
        if (gr < n) {
            float ns = g_norm_src[gr];
            float4 o;
            unpack2(acc01[r], o.x, o.y);
            unpack2(acc23[r], o.z, o.w);
            o.x *= ns; o.y *= ns; o.z *= ns; o.w *= ns;
            reinterpret_cast<float4*>(g_hw)[gr * 32 + lane] = o;
        }
    }
}

// ---------------- edge aggregation: h = relu(norm_dst ⊙ (A @ hw) + b) --------
// warp per dst node; lane owns 4 dims (float4). CSR traversal, unroll 4.
__global__ void __launch_bounds__(256) k_agg(const float* __restrict__ bias, int n) {
    int warp = (blockIdx.x * blockDim.x + threadIdx.x) >> 5;
    int lane = threadIdx.x & 31;
    if (warp >= n) return;

    int beg = g_row_ptr[warp];
    int end = g_row_ptr[warp + 1];

    const float4* hw4 = reinterpret_cast<const float4*>(g_hw);
    float4 a0 = make_float4(0.f, 0.f, 0.f, 0.f), a1 = a0, a2 = a0, a3 = a0;

    int e = beg;
    for (; e + 3 < end; e += 4) {
        int s0 = g_csr[e], s1 = g_csr[e + 1], s2 = g_csr[e + 2], s3 = g_csr[e + 3];
        a0 = f4add(a0, hw4[s0 * 32 + lane]);
        a1 = f4add(a1, hw4[s1 * 32 + lane]);
        a2 = f4add(a2, hw4[s2 * 32 + lane]);
        a3 = f4add(a3, hw4[s3 * 32 + lane]);
    }
    for (; e < end; ++e)
        a0 = f4add(a0, hw4[g_csr[e] * 32 + lane]);

    float4 a = f4add(f4add(a0, a1), f4add(a2, a3));
    float nd = g_norm_dst[warp];
    float4 bb = reinterpret_cast<const float4*>(bias)[lane];
    float4 o;
    o.x = fmaxf(fmaf(a.x, nd, bb.x), 0.f);
    o.y = fmaxf(fmaf(a.y, nd, bb.y), 0.f);
    o.z = fmaxf(fmaf(a.z, nd, bb.z), 0.f);
    o.w = fmaxf(fmaf(a.w, nd, bb.w), 0.f);
    reinterpret_cast<float4*>(g_h)[warp * 32 + lane] = o;
}

// ---------------- per-graph max readout (graph_ids sorted) -------------------
__global__ void k_readout(const int* __restrict__ gids, float* __restrict__ out, int n) {
    __shared__ int sg[512];
    int n0 = blockIdx.x * 512;
    int cnt = min(512, n - n0);
    if (cnt <= 0) return;
    for (int i = threadIdx.x; i < cnt; i += 128) sg[i] = gids[n0 + i];
    __syncthreads();

    int d = threadIdx.x;
    int cur = sg[0];
    float m = 0.f;
    for (int i = 0; i < cnt; i++) {
        int g = sg[i];
        if (g != cur) {
            atomicMax(reinterpret_cast<int*>(&out[cur * DIMV + d]), __float_as_int(m));
            m = 0.f;
            cur = g;
        }
        m = fmaxf(m, g_h[(n0 + i) * DIMV + d]);
    }
    atomicMax(reinterpret_cast<int*>(&out[cur * DIMV + d]), __float_as_int(m));
}

// ---------------- launch ------------------------------------------------------
extern "C" void kernel_launch(void* const* d_in, const int* in_sizes, int n_in,
                              void* d_out, int out_size) {
    const int*   feat_id = (const int*)  d_in[0];
    const int*   src     = (const int*)  d_in[1];
    const int*   dst     = (const int*)  d_in[2];
    const int*   gids    = (const int*)  d_in[3];
    const float* emb     = (const float*)d_in[4];
    const float* W       = (const float*)d_in[5];
    const float* b       = (const float*)d_in[6];
    float*       out     = (float*)d_out;

    int N = in_sizes[0];
    int E = in_sizes[1];
    int LAYERS = in_sizes[6] / DIMV;

    const int T = 256;
    int nbN  = (N + T - 1) / T;
    int nbE  = (E + T - 1) / T;
    int nbSc = (N + SCAN_B - 1) / SCAN_B;

    // build degrees / norms / CSR
    k_zero_counts<<<nbN, T>>>(N);
    k_hist<<<nbE, T>>>(src, dst, E);
    k_norms<<<nbN, T>>>(N);
    k_scan1<<<nbSc, SCAN_B>>>(N);
    k_scan2<<<1, SCAN_B>>>(nbSc);
    k_scan3<<<nbN, T>>>(N, E);
    k_fill<<<nbE, T>>>(src, dst, E);

    // embedding
    int embThreads = N * 32;
    k_embed<<<(embThreads + T - 1) / T, T>>>(feat_id, emb, N);

    // GEMM smem opt-in (96KB dynamic)
    size_t gemm_smem = (size_t)(DIMV * DIMV + 64 * DIMV) * sizeof(float);
    cudaFuncSetAttribute(k_gemm, cudaFuncAttributeMaxDynamicSharedMemorySize,
                         (int)gemm_smem);

    int gemmBlocks = (N + 63) / 64;
    int aggBlocks  = (N + 7) / 8;   // 8 warps/block, warp per node

    for (int l = 0; l < LAYERS; l++) {
        k_gemm<<<gemmBlocks, 256, gemm_smem>>>(W + (size_t)l * DIMV * DIMV, N);
        k_agg<<<aggBlocks, 256>>>(b + (size_t)l * DIMV, N);
    }

    // readout
    k_zero_out<<<(out_size + T - 1) / T, T>>>(out, out_size);
    k_readout<<<(N + 511) / 512, 128>>>(gids, out, N);
}

// round 3
// speedup vs baseline: 1.2317x; 1.1475x over previous
#include <cuda_runtime.h>
#include <cuda_bf16.h>
#include <cuda_fp16.h>

#define MAXN 100000
#define MAXE 1600000
#define DIMV 128
#define SCAN_B 1024

// ---------------- scratch (device globals; no allocation allowed) -------------
__device__ float  g_h [MAXN * DIMV];
__device__ __half g_hw[MAXN * DIMV];          // fp16 storage halves gather traffic
__device__ int    g_csr[MAXE];
__device__ int    g_row_ptr[MAXN + 1];
__device__ int    g_cursor[MAXN];
__device__ int    g_cnt_src[MAXN];
__device__ int    g_cnt_dst[MAXN];
__device__ float  g_norm_dst[MAXN];
__device__ int    g_spine[256];

// ---------------- packed f32x2 helpers (Blackwell) ----------------------------
__device__ __forceinline__ unsigned long long pack2(float x, float y) {
    unsigned long long r;
    asm("mov.b64 %0, {%1, %2};" : "=l"(r) : "f"(x), "f"(y));
    return r;
}
__device__ __forceinline__ void unpack2(unsigned long long v, float& x, float& y) {
    asm("mov.b64 {%0, %1}, %2;" : "=f"(x), "=f"(y) : "l"(v));
}
__device__ __forceinline__ void fma2(unsigned long long& d,
                                     unsigned long long a, unsigned long long b) {
    asm("fma.rn.f32x2 %0, %1, %2, %0;" : "+l"(d) : "l"(a), "l"(b));
}

// ---------------- zero counters ----------------------------------------------
__global__ void k_zero_counts(int n) {
    int i = blockIdx.x * blockDim.x + threadIdx.x;
    if (i < n) { g_cnt_src[i] = 0; g_cnt_dst[i] = 0; }
}

__global__ void k_zero_out(float* out, int n) {
    int i = blockIdx.x * blockDim.x + threadIdx.x;
    if (i < n) out[i] = 0.0f;
}

// ---------------- degree histograms ------------------------------------------
__global__ void k_hist(const int* __restrict__ src, const int* __restrict__ dst, int E) {
    int e = blockIdx.x * blockDim.x + threadIdx.x;
    if (e < E) {
        atomicAdd(&g_cnt_src[src[e]], 1);
        atomicAdd(&g_cnt_dst[dst[e]], 1);
    }
}

__global__ void k_norms(int n) {
    int i = blockIdx.x * blockDim.x + threadIdx.x;
    if (i < n) g_norm_dst[i] = rsqrtf((float)max(g_cnt_dst[i], 1));
}

// ---------------- exclusive scan of in-degree counts -> row_ptr ---------------
__global__ void k_scan1(int n) {
    __shared__ int s[SCAN_B];
    int i = blockIdx.x * SCAN_B + threadIdx.x;
    int v = (i < n) ? g_cnt_dst[i] : 0;
    s[threadIdx.x] = v;
    __syncthreads();
    for (int off = 1; off < SCAN_B; off <<= 1) {
        int t = (threadIdx.x >= off) ? s[threadIdx.x - off] : 0;
        __syncthreads();
        s[threadIdx.x] += t;
        __syncthreads();
    }
    if (i < n) g_row_ptr[i] = s[threadIdx.x] - v;   // exclusive within block
    if (threadIdx.x == SCAN_B - 1) g_spine[blockIdx.x] = s[SCAN_B - 1];
}

__global__ void k_scan2(int nb) {
    __shared__ int s[SCAN_B];
    int v = (threadIdx.x < nb) ? g_spine[threadIdx.x] : 0;
    s[threadIdx.x] = v;
    __syncthreads();
    for (int off = 1; off < SCAN_B; off <<= 1) {
        int t = (threadIdx.x >= off) ? s[threadIdx.x - off] : 0;
        __syncthreads();
        s[threadIdx.x] += t;
        __syncthreads();
    }
    if (threadIdx.x < nb) g_spine[threadIdx.x] = s[threadIdx.x] - v; // exclusive
}

__global__ void k_scan3(int n, int E) {
    int i = blockIdx.x * blockDim.x + threadIdx.x;
    if (i < n) {
        int r = g_row_ptr[i] + g_spine[i / SCAN_B];
        g_row_ptr[i] = r;
        g_cursor[i]  = r;
    }
    if (i == 0) g_row_ptr[n] = E;
}

// ---------------- CSR fill (counting sort of edges by dst) -------------------
__global__ void k_fill(const int* __restrict__ src, const int* __restrict__ dst, int E) {
    int e = blockIdx.x * blockDim.x + threadIdx.x;
    if (e < E) {
        int pos = atomicAdd(&g_cursor[dst[e]], 1);
        g_csr[pos] = src[e];
    }
}

// ---------------- embedding gather -------------------------------------------
__global__ void k_embed(const int* __restrict__ feat_id, const float* __restrict__ emb, int n) {
    int idx = blockIdx.x * blockDim.x + threadIdx.x;   // over n*32 float4s
    if (idx < n * 32) {
        int node = idx >> 5;
        int c    = idx & 31;
        reinterpret_cast<float4*>(g_h)[idx] =
            reinterpret_cast<const float4*>(emb)[feat_id[node] * 32 + c];
    }
}

// ---------------- GEMM: hw = norm_src ⊙ (h @ W), fp16 output -----------------
// block: 256 threads, 64 rows; W (64KB) + 64 h-rows (32KB) in dynamic smem.
// warp handles 8 rows; lane owns 4 output cols as two packed f32x2 accumulators.
// norm_src computed inline from cnt_src (rsqrt) -> no dependency on k_norms.
__global__ void __launch_bounds__(256) k_gemm(const float* __restrict__ W, int n) {
    extern __shared__ float smem[];
    float* Ws = smem;                 // 128*128
    float* hs = smem + DIMV * DIMV;   // 64*128
    int tid = threadIdx.x;

    // load W
    for (int i = tid; i < DIMV * DIMV / 4; i += 256)
        reinterpret_cast<float4*>(Ws)[i] = reinterpret_cast<const float4*>(W)[i];

    int row0 = blockIdx.x * 64;
    // load 64 rows of h
    for (int i = tid; i < 64 * 32; i += 256) {
        int r = i >> 5, c = i & 31;
        int gr = row0 + r;
        reinterpret_cast<float4*>(hs)[i] =
            (gr < n) ? reinterpret_cast<const float4*>(g_h)[gr * 32 + c]
                     : make_float4(0.f, 0.f, 0.f, 0.f);
    }
    __syncthreads();

    int warp = tid >> 5, lane = tid & 31;
    const float4* hb4 = reinterpret_cast<const float4*>(hs + (warp * 8) * DIMV);
    const float4* Ws4 = reinterpret_cast<const float4*>(Ws);

    unsigned long long acc01[8], acc23[8];
#pragma unroll
    for (int r = 0; r < 8; r++) { acc01[r] = 0ull; acc23[r] = 0ull; }

    for (int k0 = 0; k0 < DIMV; k0 += 4) {
        float4 av[8];
#pragma unroll
        for (int r = 0; r < 8; r++)
            av[r] = hb4[r * 32 + (k0 >> 2)];        // broadcast across warp

#pragma unroll
        for (int kk = 0; kk < 4; kk++) {
            float4 w = Ws4[(k0 + kk) * 32 + lane];
            unsigned long long w01 = pack2(w.x, w.y);
            unsigned long long w23 = pack2(w.z, w.w);
#pragma unroll
            for (int r = 0; r < 8; r++) {
                float a = reinterpret_cast<const float*>(&av[r])[kk];
                unsigned long long aa = pack2(a, a);
                fma2(acc01[r], aa, w01);
                fma2(acc23[r], aa, w23);
            }
        }
    }

#pragma unroll
    for (int r = 0; r < 8; r++) {
        int gr = row0 + warp * 8 + r;
        if (gr < n) {
            float ns = rsqrtf((float)max(g_cnt_src[gr], 1));
            float x, y, z, w2;
            unpack2(acc01[r], x, y);
            unpack2(acc23[r], z, w2);
            __half2 p0 = __floats2half2_rn(x * ns, y * ns);
            __half2 p1 = __floats2half2_rn(z * ns, w2 * ns);
            uint2 v;
            v.x = *reinterpret_cast<unsigned int*>(&p0);
            v.y = *reinterpret_cast<unsigned int*>(&p1);
            reinterpret_cast<uint2*>(g_hw)[gr * 32 + lane] = v;
        }
    }
}

// ---------------- edge aggregation: h = relu(norm_dst ⊙ (A @ hw) + b) --------
// warp per dst node; lane owns 4 dims (8B fp16 load), fp32 accumulate.
__global__ void __launch_bounds__(256) k_agg(const float* __restrict__ bias, int n) {
    int warp = (blockIdx.x * blockDim.x + threadIdx.x) >> 5;
    int lane = threadIdx.x & 31;
    if (warp >= n) return;

    int beg = g_row_ptr[warp];
    int end = g_row_ptr[warp + 1];

    const uint2* hw2 = reinterpret_cast<const uint2*>(g_hw);  // row = 32 uint2
    float ax0 = 0.f, ay0 = 0.f, az0 = 0.f, aw0 = 0.f;
    float ax1 = 0.f, ay1 = 0.f, az1 = 0.f, aw1 = 0.f;

    int e = beg;
    for (; e + 3 < end; e += 4) {
        int s0 = g_csr[e], s1 = g_csr[e + 1], s2 = g_csr[e + 2], s3 = g_csr[e + 3];
        uint2 v0 = hw2[s0 * 32 + lane];
        uint2 v1 = hw2[s1 * 32 + lane];
        uint2 v2 = hw2[s2 * 32 + lane];
        uint2 v3 = hw2[s3 * 32 + lane];
        float2 f0a = __half22float2(*reinterpret_cast<__half2*>(&v0.x));
        float2 f0b = __half22float2(*reinterpret_cast<__half2*>(&v0.y));
        float2 f1a = __half22float2(*reinterpret_cast<__half2*>(&v1.x));
        float2 f1b = __half22float2(*reinterpret_cast<__half2*>(&v1.y));
        float2 f2a = __half22float2(*reinterpret_cast<__half2*>(&v2.x));
        float2 f2b = __half22float2(*reinterpret_cast<__half2*>(&v2.y));
        float2 f3a = __half22float2(*reinterpret_cast<__half2*>(&v3.x));
        float2 f3b = __half22float2(*reinterpret_cast<__half2*>(&v3.y));
        ax0 += f0a.x; ay0 += f0a.y; az0 += f0b.x; aw0 += f0b.y;
        ax1 += f1a.x; ay1 += f1a.y; az1 += f1b.x; aw1 += f1b.y;
        ax0 += f2a.x; ay0 += f2a.y; az0 += f2b.x; aw0 += f2b.y;
        ax1 += f3a.x; ay1 += f3a.y; az1 += f3b.x; aw1 += f3b.y;
    }
    for (; e < end; ++e) {
        uint2 v = hw2[g_csr[e] * 32 + lane];
        float2 fa = __half22float2(*reinterpret_cast<__half2*>(&v.x));
        float2 fb = __half22float2(*reinterpret_cast<__half2*>(&v.y));
        ax0 += fa.x; ay0 += fa.y; az0 += fb.x; aw0 += fb.y;
    }

    float nd = g_norm_dst[warp];
    float4 bb = reinterpret_cast<const float4*>(bias)[lane];
    float4 o;
    o.x = fmaxf(fmaf(ax0 + ax1, nd, bb.x), 0.f);
    o.y = fmaxf(fmaf(ay0 + ay1, nd, bb.y), 0.f);
    o.z = fmaxf(fmaf(az0 + az1, nd, bb.z), 0.f);
    o.w = fmaxf(fmaf(aw0 + aw1, nd, bb.w), 0.f);
    reinterpret_cast<float4*>(g_h)[warp * 32 + lane] = o;
}

// ---------------- per-graph max readout (graph_ids sorted) -------------------
__global__ void k_readout(const int* __restrict__ gids, float* __restrict__ out, int n) {
    __shared__ int sg[512];
    int n0 = blockIdx.x * 512;
    int cnt = min(512, n - n0);
    if (cnt <= 0) return;
    for (int i = threadIdx.x; i < cnt; i += 128) sg[i] = gids[n0 + i];
    __syncthreads();

    int d = threadIdx.x;
    int cur = sg[0];
    float m = 0.f;
    for (int i = 0; i < cnt; i++) {
        int g = sg[i];
        if (g != cur) {
            atomicMax(reinterpret_cast<int*>(&out[cur * DIMV + d]), __float_as_int(m));
            m = 0.f;
            cur = g;
        }
        m = fmaxf(m, g_h[(n0 + i) * DIMV + d]);
    }
    atomicMax(reinterpret_cast<int*>(&out[cur * DIMV + d]), __float_as_int(m));
}

// ---------------- launch ------------------------------------------------------
extern "C" void kernel_launch(void* const* d_in, const int* in_sizes, int n_in,
                              void* d_out, int out_size) {
    const int*   feat_id = (const int*)  d_in[0];
    const int*   src     = (const int*)  d_in[1];
    const int*   dst     = (const int*)  d_in[2];
    const int*   gids    = (const int*)  d_in[3];
    const float* emb     = (const float*)d_in[4];
    const float* W       = (const float*)d_in[5];
    const float* b       = (const float*)d_in[6];
    float*       out     = (float*)d_out;

    int N = in_sizes[0];
    int E = in_sizes[1];
    int LAYERS = in_sizes[6] / DIMV;

    const int T = 256;
    int nbN  = (N + T - 1) / T;
    int nbE  = (E + T - 1) / T;
    int nbSc = (N + SCAN_B - 1) / SCAN_B;

    size_t gemm_smem = (size_t)(DIMV * DIMV + 64 * DIMV) * sizeof(float);
    cudaFuncSetAttribute(k_gemm, cudaFuncAttributeMaxDynamicSharedMemorySize,
                         (int)gemm_smem);

    int gemmBlocks = (N + 63) / 64;
    int aggBlocks  = (N + 7) / 8;   // 8 warps/block, warp per node

    // order chosen so k_gemm is our 4th launch -> lands in the ncu capture slot
    k_zero_counts<<<nbN, T>>>(N);                                   // 0
    k_hist<<<nbE, T>>>(src, dst, E);                                // 1
    k_embed<<<(N * 32 + T - 1) / T, T>>>(feat_id, emb, N);          // 2
    k_gemm<<<gemmBlocks, 256, gemm_smem>>>(W, N);                   // 3  <- profiled

    k_norms<<<nbN, T>>>(N);
    k_scan1<<<nbSc, SCAN_B>>>(N);
    k_scan2<<<1, SCAN_B>>>(nbSc);
    k_scan3<<<nbN, T>>>(N, E);
    k_fill<<<nbE, T>>>(src, dst, E);

    k_agg<<<aggBlocks, 256>>>(b, N);
    for (int l = 1; l < LAYERS; l++) {
        k_gemm<<<gemmBlocks, 256, gemm_smem>>>(W + (size_t)l * DIMV * DIMV, N);
        k_agg<<<aggBlocks, 256>>>(b + (size_t)l * DIMV, N);
    }

    // readout
    k_zero_out<<<(out_size + T - 1) / T, T>>>(out, out_size);
    k_readout<<<(N + 511) / 512, 128>>>(gids, out, N);
}

// round 5
// speedup vs baseline: 2.1302x; 1.7295x over previous
#include <cuda_runtime.h>
#include <cuda_bf16.h>
#include <cuda_fp16.h>
#include <cstdint>

#define MAXN 100000
#define MAXE 1600000
#define DIMV 128
#define SCAN_B 1024
#define MAXL 8
#define ASTH 136           // padded smem stride in halves
#define ASTB 272           // padded smem stride in bytes

// ---------------- scratch (device globals; no allocation allowed) -------------
__device__ __align__(256) __half g_hf[MAXN * DIMV];        // node features (fp16)
__device__ __align__(256) __half g_hw[MAXN * DIMV];        // h @ W * norm_src (fp16)
__device__ __align__(256) __half g_wt[MAXL * DIMV * DIMV]; // W^T per layer (fp16)
__device__ int    g_csr[MAXE];
__device__ int    g_row_ptr[MAXN + 1];
__device__ int    g_cursor[MAXN];
__device__ int    g_cnt_src[MAXN];
__device__ int    g_cnt_dst[MAXN];
__device__ float  g_norm_dst[MAXN];
__device__ int    g_spine[256];

// ---------------- PTX helpers (base-PTX only: ldmatrix/stmatrix/mma) ----------
__device__ __forceinline__ uint32_t smem_u32(const void* p) {
    uint32_t a;
    asm("{ .reg .u64 t; cvta.to.shared.u64 t, %1; cvt.u32.u64 %0, t; }" : "=r"(a) : "l"(p));
    return a;
}
__device__ __forceinline__ void ldsm_x4(uint32_t& r0, uint32_t& r1, uint32_t& r2,
                                        uint32_t& r3, uint32_t addr) {
    asm volatile("ldmatrix.sync.aligned.m8n8.x4.shared.b16 {%0,%1,%2,%3}, [%4];"
                 : "=r"(r0), "=r"(r1), "=r"(r2), "=r"(r3) : "r"(addr));
}
__device__ __forceinline__ void stsm_x4(uint32_t addr, uint32_t r0, uint32_t r1,
                                        uint32_t r2, uint32_t r3) {
    asm volatile("stmatrix.sync.aligned.m8n8.x4.shared.b16 [%0], {%1,%2,%3,%4};"
                 :: "r"(addr), "r"(r0), "r"(r1), "r"(r2), "r"(r3) : "memory");
}
__device__ __forceinline__ void mma16816(float* c, uint32_t a0, uint32_t a1,
                                         uint32_t a2, uint32_t a3,
                                         uint32_t b0, uint32_t b1) {
    asm volatile("mma.sync.aligned.m16n8k16.row.col.f32.f16.f16.f32 "
                 "{%0,%1,%2,%3}, {%4,%5,%6,%7}, {%8,%9}, {%0,%1,%2,%3};"
                 : "+f"(c[0]), "+f"(c[1]), "+f"(c[2]), "+f"(c[3])
                 : "r"(a0), "r"(a1), "r"(a2), "r"(a3), "r"(b0), "r"(b1));
}

// ---------------- prep: zero counters + transpose W to fp16 -------------------
__global__ void k_prep(const float* __restrict__ W, int nbN, int n, int layers) {
    int b = blockIdx.x;
    if (b < nbN) {
        int i = b * 256 + threadIdx.x;
        if (i < n) { g_cnt_src[i] = 0; g_cnt_dst[i] = 0; }
    } else {
        int l = b - nbN;
        if (l < layers) {
            const float* Wl = W + (size_t)l * DIMV * DIMV;
            __half* Wt = g_wt + (size_t)l * DIMV * DIMV;
            for (int i = threadIdx.x; i < DIMV * DIMV; i += 256) {
                int nr = i >> 7, k = i & 127;
                Wt[nr * DIMV + k] = __float2half(Wl[k * DIMV + nr]);
            }
        }
    }
}

__global__ void k_zero_out(float* out, int n) {
    int i = blockIdx.x * blockDim.x + threadIdx.x;
    if (i < n) out[i] = 0.0f;
}

// ---------------- degree histograms ------------------------------------------
__global__ void k_hist(const int* __restrict__ src, const int* __restrict__ dst, int E) {
    int e = blockIdx.x * blockDim.x + threadIdx.x;
    if (e < E) {
        atomicAdd(&g_cnt_src[src[e]], 1);
        atomicAdd(&g_cnt_dst[dst[e]], 1);
    }
}

__global__ void k_norms(int n) {
    int i = blockIdx.x * blockDim.x + threadIdx.x;
    if (i < n) g_norm_dst[i] = rsqrtf((float)max(g_cnt_dst[i], 1));
}

// ---------------- exclusive scan of in-degree counts -> row_ptr ---------------
__global__ void k_scan1(int n) {
    __shared__ int s[SCAN_B];
    int i = blockIdx.x * SCAN_B + threadIdx.x;
    int v = (i < n) ? g_cnt_dst[i] : 0;
    s[threadIdx.x] = v;
    __syncthreads();
    for (int off = 1; off < SCAN_B; off <<= 1) {
        int t = (threadIdx.x >= off) ? s[threadIdx.x - off] : 0;
        __syncthreads();
        s[threadIdx.x] += t;
        __syncthreads();
    }
    if (i < n) g_row_ptr[i] = s[threadIdx.x] - v;
    if (threadIdx.x == SCAN_B - 1) g_spine[blockIdx.x] = s[SCAN_B - 1];
}

__global__ void k_scan2(int nb) {
    __shared__ int s[SCAN_B];
    int v = (threadIdx.x < nb) ? g_spine[threadIdx.x] : 0;
    s[threadIdx.x] = v;
    __syncthreads();
    for (int off = 1; off < SCAN_B; off <<= 1) {
        int t = (threadIdx.x >= off) ? s[threadIdx.x - off] : 0;
        __syncthreads();
        s[threadIdx.x] += t;
        __syncthreads();
    }
    if (threadIdx.x < nb) g_spine[threadIdx.x] = s[threadIdx.x] - v;
}

__global__ void k_scan3(int n, int E) {
    int i = blockIdx.x * blockDim.x + threadIdx.x;
    if (i < n) {
        int r = g_row_ptr[i] + g_spine[i / SCAN_B];
        g_row_ptr[i] = r;
        g_cursor[i]  = r;
    }
    if (i == 0) g_row_ptr[n] = E;
}

// ---------------- CSR fill (counting sort of edges by dst) -------------------
__global__ void k_fill(const int* __restrict__ src, const int* __restrict__ dst, int E) {
    int e = blockIdx.x * blockDim.x + threadIdx.x;
    if (e < E) {
        int pos = atomicAdd(&g_cursor[dst[e]], 1);
        g_csr[pos] = src[e];
    }
}

// ---------------- embedding gather -> fp16 h ---------------------------------
__global__ void k_embed(const int* __restrict__ feat_id, const float* __restrict__ emb, int n) {
    int idx = blockIdx.x * blockDim.x + threadIdx.x;   // over n*16 uint4 outputs
    if (idx < n * 16) {
        int node = idx >> 4;
        int c    = idx & 15;
        const float4* e = reinterpret_cast<const float4*>(emb) + (size_t)feat_id[node] * 32 + c * 2;
        float4 a = e[0], b = e[1];
        __half2 h0 = __floats2half2_rn(a.x, a.y);
        __half2 h1 = __floats2half2_rn(a.z, a.w);
        __half2 h2 = __floats2half2_rn(b.x, b.y);
        __half2 h3 = __floats2half2_rn(b.z, b.w);
        uint4 v;
        v.x = *reinterpret_cast<uint32_t*>(&h0);
        v.y = *reinterpret_cast<uint32_t*>(&h1);
        v.z = *reinterpret_cast<uint32_t*>(&h2);
        v.w = *reinterpret_cast<uint32_t*>(&h3);
        reinterpret_cast<uint4*>(g_hf)[idx] = v;
    }
}

// ---------------- HMMA GEMM: hw = norm_src ⊙ (h @ W), fp16 in/out ------------
// Block = 256 threads / 8 warps, tile M=128,N=128,K=128.
// A = g_hf rows, B = W^T (n-major, so mma .col operand loads via non-trans ldmatrix).
// Epilogue: scale + fp16 convert + stmatrix into reused A-smem + uint4 stores.
#define SM_GEMM (2 * 128 * ASTB)

__global__ void __launch_bounds__(256) k_gemm_hmma(const __half* __restrict__ Wt, int n) {
    extern __shared__ char sm[];
    char* sA = sm;
    char* sB = sm + 128 * ASTB;
    int tid = threadIdx.x, warp = tid >> 5, lane = tid & 31;
    int row0 = blockIdx.x * 128;

    // load A tile (zero-pad tail rows) and B tile
    const uint4* Asrc = reinterpret_cast<const uint4*>(g_hf);
    const uint4* Bsrc = reinterpret_cast<const uint4*>(Wt);
    for (int i = tid; i < 2048; i += 256) {
        int r = i >> 4, c = i & 15;
        uint4 v = make_uint4(0u, 0u, 0u, 0u);
        if (row0 + r < n) v = Asrc[(size_t)(row0 + r) * 16 + c];
        *reinterpret_cast<uint4*>(sA + r * ASTB + c * 16) = v;
        *reinterpret_cast<uint4*>(sB + r * ASTB + c * 16) = Bsrc[i];
    }
    __syncthreads();

    int m0 = warp * 16;
    // A-fragment lane base: bit3(lane) -> row+8, bit4(lane) -> k+8
    uint32_t a_base = smem_u32(sA)
        + (m0 + (lane & 7) + ((lane & 8) ? 8 : 0)) * ASTB
        + ((lane & 16) ? 16 : 0);
    // B-fragment lane base (x4 = two n-tiles): bit3 -> k+8, bit4 -> n-row+8
    uint32_t b_base = smem_u32(sB)
        + ((lane & 7) + ((lane & 16) ? 8 : 0)) * ASTB
        + ((lane & 8) ? 16 : 0);

    float acc[16][4];
#pragma unroll
    for (int j = 0; j < 16; j++)
#pragma unroll
        for (int q = 0; q < 4; q++) acc[j][q] = 0.f;

#pragma unroll
    for (int ks = 0; ks < 8; ks++) {
        uint32_t a0, a1, a2, a3;
        ldsm_x4(a0, a1, a2, a3, a_base + ks * 32);
#pragma unroll
        for (int jj = 0; jj < 8; jj++) {
            uint32_t b0, b1, b2, b3;
            ldsm_x4(b0, b1, b2, b3, b_base + jj * 16 * ASTB + ks * 32);
            mma16816(acc[2 * jj],     a0, a1, a2, a3, b0, b1);
            mma16816(acc[2 * jj + 1], a0, a1, a2, a3, b2, b3);
        }
    }
    __syncthreads();   // all warps done reading smem A/B

    int mr0 = row0 + m0 + (lane >> 2);
    int mr1 = mr0 + 8;
    float ns0 = (mr0 < n) ? rsqrtf((float)max(g_cnt_src[mr0], 1)) : 0.f;
    float ns1 = (mr1 < n) ? rsqrtf((float)max(g_cnt_src[mr1], 1)) : 0.f;

    // stmatrix staging into reused A smem: bit3 -> row+8, bit4 -> second n-tile
    uint32_t st_base = smem_u32(sA)
        + (m0 + (lane & 7) + ((lane & 8) ? 8 : 0)) * ASTB
        + ((lane & 16) ? 16 : 0);
#pragma unroll
    for (int jj = 0; jj < 8; jj++) {
        __half2 t0lo = __floats2half2_rn(acc[2*jj][0] * ns0,   acc[2*jj][1] * ns0);
        __half2 t0hi = __floats2half2_rn(acc[2*jj][2] * ns1,   acc[2*jj][3] * ns1);
        __half2 t1lo = __floats2half2_rn(acc[2*jj+1][0] * ns0, acc[2*jj+1][1] * ns0);
        __half2 t1hi = __floats2half2_rn(acc[2*jj+1][2] * ns1, acc[2*jj+1][3] * ns1);
        stsm_x4(st_base + jj * 32,
                *reinterpret_cast<uint32_t*>(&t0lo),
                *reinterpret_cast<uint32_t*>(&t0hi),
                *reinterpret_cast<uint32_t*>(&t1lo),
                *reinterpret_cast<uint32_t*>(&t1hi));
    }
    __syncthreads();

    for (int i = tid; i < 2048; i += 256) {
        int r = i >> 4, c = i & 15;
        int gr = row0 + r;
        if (gr < n)
            reinterpret_cast<uint4*>(g_hw)[(size_t)gr * 16 + c] =
                *reinterpret_cast<uint4*>(sA + r * ASTB + c * 16);
    }
}

// ---------------- edge aggregation: h = relu(norm_dst ⊙ (A @ hw) + b) --------
// warp per dst node; lane owns 4 dims (8B fp16 load), fp32 accumulate, fp16 out.
__global__ void __launch_bounds__(256) k_agg(const float* __restrict__ bias, int n) {
    int warp = (blockIdx.x * blockDim.x + threadIdx.x) >> 5;
    int lane = threadIdx.x & 31;
    if (warp >= n) return;

    int beg = g_row_ptr[warp];
    int end = g_row_ptr[warp + 1];

    const uint2* hw2 = reinterpret_cast<const uint2*>(g_hw);
    float ax0 = 0.f, ay0 = 0.f, az0 = 0.f, aw0 = 0.f;
    float ax1 = 0.f, ay1 = 0.f, az1 = 0.f, aw1 = 0.f;

    int e = beg;
    for (; e + 3 < end; e += 4) {
        int s0 = g_csr[e], s1 = g_csr[e + 1], s2 = g_csr[e + 2], s3 = g_csr[e + 3];
        uint2 v0 = hw2[(size_t)s0 * 32 + lane];
        uint2 v1 = hw2[(size_t)s1 * 32 + lane];
        uint2 v2 = hw2[(size_t)s2 * 32 + lane];
        uint2 v3 = hw2[(size_t)s3 * 32 + lane];
        float2 f0a = __half22float2(*reinterpret_cast<__half2*>(&v0.x));
        float2 f0b = __half22float2(*reinterpret_cast<__half2*>(&v0.y));
        float2 f1a = __half22float2(*reinterpret_cast<__half2*>(&v1.x));
        float2 f1b = __half22float2(*reinterpret_cast<__half2*>(&v1.y));
        float2 f2a = __half22float2(*reinterpret_cast<__half2*>(&v2.x));
        float2 f2b = __half22float2(*reinterpret_cast<__half2*>(&v2.y));
        float2 f3a = __half22float2(*reinterpret_cast<__half2*>(&v3.x));
        float2 f3b = __half22float2(*reinterpret_cast<__half2*>(&v3.y));
        ax0 += f0a.x; ay0 += f0a.y; az0 += f0b.x; aw0 += f0b.y;
        ax1 += f1a.x; ay1 += f1a.y; az1 += f1b.x; aw1 += f1b.y;
        ax0 += f2a.x; ay0 += f2a.y; az0 += f2b.x; aw0 += f2b.y;
        ax1 += f3a.x; ay1 += f3a.y; az1 += f3b.x; aw1 += f3b.y;
    }
    for (; e < end; ++e) {
        uint2 v = hw2[(size_t)g_csr[e] * 32 + lane];
        float2 fa = __half22float2(*reinterpret_cast<__half2*>(&v.x));
        float2 fb = __half22float2(*reinterpret_cast<__half2*>(&v.y));
        ax0 += fa.x; ay0 += fa.y; az0 += fb.x; aw0 += fb.y;
    }

    float nd = g_norm_dst[warp];
    float4 bb = reinterpret_cast<const float4*>(bias)[lane];
    float ox = fmaxf(fmaf(ax0 + ax1, nd, bb.x), 0.f);
    float oy = fmaxf(fmaf(ay0 + ay1, nd, bb.y), 0.f);
    float oz = fmaxf(fmaf(az0 + az1, nd, bb.z), 0.f);
    float ow = fmaxf(fmaf(aw0 + aw1, nd, bb.w), 0.f);
    __half2 p0 = __floats2half2_rn(ox, oy);
    __half2 p1 = __floats2half2_rn(oz, ow);
    uint2 o;
    o.x = *reinterpret_cast<uint32_t*>(&p0);
    o.y = *reinterpret_cast<uint32_t*>(&p1);
    reinterpret_cast<uint2*>(g_hf)[(size_t)warp * 32 + lane] = o;
}

// ---------------- per-graph max readout (graph_ids sorted) -------------------
__global__ void k_readout(const int* __restrict__ gids, float* __restrict__ out, int n) {
    __shared__ int sg[512];
    int n0 = blockIdx.x * 512;
    int cnt = min(512, n - n0);
    if (cnt <= 0) return;
    for (int i = threadIdx.x; i < cnt; i += 128) sg[i] = gids[n0 + i];
    __syncthreads();

    int d = threadIdx.x;
    int cur = sg[0];
    float m = 0.f;
    for (int i = 0; i < cnt; i++) {
        int g = sg[i];
        if (g != cur) {
            atomicMax(reinterpret_cast<int*>(&out[cur * DIMV + d]), __float_as_int(m));
            m = 0.f;
            cur = g;
        }
        m = fmaxf(m, __half2float(g_hf[(size_t)(n0 + i) * DIMV + d]));
    }
    atomicMax(reinterpret_cast<int*>(&out[cur * DIMV + d]), __float_as_int(m));
}

// ---------------- launch ------------------------------------------------------
extern "C" void kernel_launch(void* const* d_in, const int* in_sizes, int n_in,
                              void* d_out, int out_size) {
    const int*   feat_id = (const int*)  d_in[0];
    const int*   src     = (const int*)  d_in[1];
    const int*   dst     = (const int*)  d_in[2];
    const int*   gids    = (const int*)  d_in[3];
    const float* emb     = (const float*)d_in[4];
    const float* W       = (const float*)d_in[5];
    const float* b       = (const float*)d_in[6];
    float*       out     = (float*)d_out;

    int N = in_sizes[0];
    int E = in_sizes[1];
    int LAYERS = in_sizes[6] / DIMV;

    const int T = 256;
    int nbN  = (N + T - 1) / T;
    int nbE  = (E + T - 1) / T;
    int nbSc = (N + SCAN_B - 1) / SCAN_B;

    cudaFuncSetAttribute(k_gemm_hmma, cudaFuncAttributeMaxDynamicSharedMemorySize, SM_GEMM);

    int tiles = (N + 127) / 128;
    int aggBlocks = (N + 7) / 8;   // 8 warps/block, warp per node

    __half* wt_dev = nullptr;
    cudaGetSymbolAddress((void**)&wt_dev, g_wt);

    // ordered so k_gemm_hmma is launch #3 (ncu capture slot)
    k_prep<<<nbN + LAYERS, T>>>(W, nbN, N, LAYERS);                 // 0
    k_hist<<<nbE, T>>>(src, dst, E);                                // 1
    k_embed<<<(N * 16 + T - 1) / T, T>>>(feat_id, emb, N);          // 2
    k_gemm_hmma<<<tiles, 256, SM_GEMM>>>(wt_dev, N);                // 3  <- profiled

    k_norms<<<nbN, T>>>(N);
    k_scan1<<<nbSc, SCAN_B>>>(N);
    k_scan2<<<1, SCAN_B>>>(nbSc);
    k_scan3<<<nbN, T>>>(N, E);
    k_fill<<<nbE, T>>>(src, dst, E);

    k_agg<<<aggBlocks, 256>>>(b, N);
    for (int l = 1; l < LAYERS; l++) {
        k_gemm_hmma<<<tiles, 256, SM_GEMM>>>(wt_dev + (size_t)l * DIMV * DIMV, N);
        k_agg<<<aggBlocks, 256>>>(b + (size_t)l * DIMV, N);
    }

    k_zero_out<<<(out_size + T - 1) / T, T>>>(out, out_size);
    k_readout<<<(N + 511) / 512, 128>>>(gids, out, N);
}

// round 6
// speedup vs baseline: 2.1877x; 1.0270x over previous
#include <cuda_runtime.h>
#include <cuda_bf16.h>
#include <cuda_fp16.h>
#include <cstdint>

#define MAXN 100000
#define MAXE 1600000
#define DIMV 128
#define SCAN_B 1024
#define MAXL 8
#define ASTH 136           // padded smem stride in halves
#define ASTB 272           // padded smem stride in bytes

// ---------------- scratch (device globals; no allocation allowed) -------------
__device__ __align__(256) __half g_hf[MAXN * DIMV];        // node features (fp16)
__device__ __align__(256) __half g_hw[MAXN * DIMV];        // h @ W * norm_src (fp16)
__device__ __align__(256) __half g_wt[MAXL * DIMV * DIMV]; // W^T per layer (fp16)
__device__ int    g_csr[MAXE];
__device__ int    g_row_ptr[MAXN + 1];
__device__ int    g_cursor[MAXN];
__device__ int    g_cnt_src[MAXN];
__device__ int    g_cnt_dst[MAXN];
__device__ float  g_norm_dst[MAXN];
__device__ int    g_spine[256];

// ---------------- PTX helpers (base-PTX: ldmatrix/stmatrix/mma/cp.async) ------
__device__ __forceinline__ uint32_t smem_u32(const void* p) {
    uint32_t a;
    asm("{ .reg .u64 t; cvta.to.shared.u64 t, %1; cvt.u32.u64 %0, t; }" : "=r"(a) : "l"(p));
    return a;
}
__device__ __forceinline__ void ldsm_x4(uint32_t& r0, uint32_t& r1, uint32_t& r2,
                                        uint32_t& r3, uint32_t addr) {
    asm volatile("ldmatrix.sync.aligned.m8n8.x4.shared.b16 {%0,%1,%2,%3}, [%4];"
                 : "=r"(r0), "=r"(r1), "=r"(r2), "=r"(r3) : "r"(addr));
}
__device__ __forceinline__ void stsm_x4(uint32_t addr, uint32_t r0, uint32_t r1,
                                        uint32_t r2, uint32_t r3) {
    asm volatile("stmatrix.sync.aligned.m8n8.x4.shared.b16 [%0], {%1,%2,%3,%4};"
                 :: "r"(addr), "r"(r0), "r"(r1), "r"(r2), "r"(r3) : "memory");
}
__device__ __forceinline__ void mma16816(float* c, uint32_t a0, uint32_t a1,
                                         uint32_t a2, uint32_t a3,
                                         uint32_t b0, uint32_t b1) {
    asm volatile("mma.sync.aligned.m16n8k16.row.col.f32.f16.f16.f32 "
                 "{%0,%1,%2,%3}, {%4,%5,%6,%7}, {%8,%9}, {%0,%1,%2,%3};"
                 : "+f"(c[0]), "+f"(c[1]), "+f"(c[2]), "+f"(c[3])
                 : "r"(a0), "r"(a1), "r"(a2), "r"(a3), "r"(b0), "r"(b1));
}
__device__ __forceinline__ void cp16(uint32_t daddr, const void* gaddr, int srcbytes) {
    asm volatile("cp.async.cg.shared.global [%0], [%1], 16, %2;"
                 :: "r"(daddr), "l"(gaddr), "r"(srcbytes) : "memory");
}
__device__ __forceinline__ void cp_commit_wait0() {
    asm volatile("cp.async.commit_group;\n\tcp.async.wait_group 0;" ::: "memory");
}

// ---------------- prep: zero counters + transpose W + zero out ----------------
__global__ void k_prep(const float* __restrict__ W, int nbN, int n, int layers,
                       float* __restrict__ out, int out_n) {
    int b = blockIdx.x;
    if (b < nbN) {
        int i = b * 256 + threadIdx.x;
        if (i < n) { g_cnt_src[i] = 0; g_cnt_dst[i] = 0; }
    } else if (b < nbN + layers) {
        int l = b - nbN;
        const float* Wl = W + (size_t)l * DIMV * DIMV;
        __half* Wt = g_wt + (size_t)l * DIMV * DIMV;
        for (int i = threadIdx.x; i < DIMV * DIMV; i += 256) {
            int nr = i >> 7, k = i & 127;
            Wt[nr * DIMV + k] = __float2half(Wl[k * DIMV + nr]);
        }
    } else {
        int i = (b - nbN - layers) * 256 + threadIdx.x;
        if (i < out_n) out[i] = 0.0f;
    }
}

// ---------------- degree histograms (4 edges/thread) --------------------------
__global__ void k_hist(const int* __restrict__ src, const int* __restrict__ dst, int E) {
    int q = blockIdx.x * blockDim.x + threadIdx.x;
    int e0 = q * 4;
    if (e0 + 3 < E) {
        int4 s = *reinterpret_cast<const int4*>(src + e0);
        int4 d = *reinterpret_cast<const int4*>(dst + e0);
        atomicAdd(&g_cnt_src[s.x], 1); atomicAdd(&g_cnt_src[s.y], 1);
        atomicAdd(&g_cnt_src[s.z], 1); atomicAdd(&g_cnt_src[s.w], 1);
        atomicAdd(&g_cnt_dst[d.x], 1); atomicAdd(&g_cnt_dst[d.y], 1);
        atomicAdd(&g_cnt_dst[d.z], 1); atomicAdd(&g_cnt_dst[d.w], 1);
    } else {
        for (int e = e0; e < E; ++e) {
            atomicAdd(&g_cnt_src[src[e]], 1);
            atomicAdd(&g_cnt_dst[dst[e]], 1);
        }
    }
}

// ---------------- scan of in-degree counts -> row_ptr (+ norm_dst) ------------
__global__ void k_scan1(int n) {
    __shared__ int s[SCAN_B];
    int i = blockIdx.x * SCAN_B + threadIdx.x;
    int v = (i < n) ? g_cnt_dst[i] : 0;
    if (i < n) g_norm_dst[i] = rsqrtf((float)max(v, 1));   // fused norm
    s[threadIdx.x] = v;
    __syncthreads();
    for (int off = 1; off < SCAN_B; off <<= 1) {
        int t = (threadIdx.x >= off) ? s[threadIdx.x - off] : 0;
        __syncthreads();
        s[threadIdx.x] += t;
        __syncthreads();
    }
    if (i < n) g_row_ptr[i] = s[threadIdx.x] - v;
    if (threadIdx.x == SCAN_B - 1) g_spine[blockIdx.x] = s[SCAN_B - 1];
}

__global__ void k_scan2(int nb) {
    __shared__ int s[SCAN_B];
    int v = (threadIdx.x < nb) ? g_spine[threadIdx.x] : 0;
    s[threadIdx.x] = v;
    __syncthreads();
    for (int off = 1; off < SCAN_B; off <<= 1) {
        int t = (threadIdx.x >= off) ? s[threadIdx.x - off] : 0;
        __syncthreads();
        s[threadIdx.x] += t;
        __syncthreads();
    }
    if (threadIdx.x < nb) g_spine[threadIdx.x] = s[threadIdx.x] - v;
}

__global__ void k_scan3(int n, int E) {
    int i = blockIdx.x * blockDim.x + threadIdx.x;
    if (i < n) {
        int r = g_row_ptr[i] + g_spine[i / SCAN_B];
        g_row_ptr[i] = r;
        g_cursor[i]  = r;
    }
    if (i == 0) g_row_ptr[n] = E;
}

// ---------------- CSR fill (counting sort by dst, 4 edges/thread) -------------
__global__ void k_fill(const int* __restrict__ src, const int* __restrict__ dst, int E) {
    int q = blockIdx.x * blockDim.x + threadIdx.x;
    int e0 = q * 4;
    if (e0 + 3 < E) {
        int4 s = *reinterpret_cast<const int4*>(src + e0);
        int4 d = *reinterpret_cast<const int4*>(dst + e0);
        g_csr[atomicAdd(&g_cursor[d.x], 1)] = s.x;
        g_csr[atomicAdd(&g_cursor[d.y], 1)] = s.y;
        g_csr[atomicAdd(&g_cursor[d.z], 1)] = s.z;
        g_csr[atomicAdd(&g_cursor[d.w], 1)] = s.w;
    } else {
        for (int e = e0; e < E; ++e)
            g_csr[atomicAdd(&g_cursor[dst[e]], 1)] = src[e];
    }
}

// ---------------- embedding gather -> fp16 h ---------------------------------
__global__ void k_embed(const int* __restrict__ feat_id, const float* __restrict__ emb, int n) {
    int idx = blockIdx.x * blockDim.x + threadIdx.x;   // over n*16 uint4 outputs
    if (idx < n * 16) {
        int node = idx >> 4;
        int c    = idx & 15;
        const float4* e = reinterpret_cast<const float4*>(emb) + (size_t)feat_id[node] * 32 + c * 2;
        float4 a = e[0], b = e[1];
        __half2 h0 = __floats2half2_rn(a.x, a.y);
        __half2 h1 = __floats2half2_rn(a.z, a.w);
        __half2 h2 = __floats2half2_rn(b.x, b.y);
        __half2 h3 = __floats2half2_rn(b.z, b.w);
        uint4 v;
        v.x = *reinterpret_cast<uint32_t*>(&h0);
        v.y = *reinterpret_cast<uint32_t*>(&h1);
        v.z = *reinterpret_cast<uint32_t*>(&h2);
        v.w = *reinterpret_cast<uint32_t*>(&h3);
        reinterpret_cast<uint4*>(g_hf)[idx] = v;
    }
}

// ---------------- HMMA GEMM: hw = norm_src ⊙ (h @ W), fp16 in/out ------------
// Block = 256 threads / 8 warps as 4(M) x 2(N). Warp tile M=32, N=64.
// cp.async tile loads; per warp: 16 A-ldsm + 32 B-ldsm + 128 MMAs.
#define SM_GEMM (2 * 128 * ASTB)

__global__ void __launch_bounds__(256) k_gemm_hmma(const __half* __restrict__ Wt, int n) {
    extern __shared__ char sm[];
    char* sA = sm;
    char* sB = sm + 128 * ASTB;
    uint32_t sAu = smem_u32(sA), sBu = smem_u32(sB);
    int tid = threadIdx.x, warp = tid >> 5, lane = tid & 31;
    int row0 = blockIdx.x * 128;

    // async tile loads (A zero-filled past n)
    const uint4* Asrc = reinterpret_cast<const uint4*>(g_hf);
    const uint4* Bsrc = reinterpret_cast<const uint4*>(Wt);
    for (int i = tid; i < 2048; i += 256) {
        int r = i >> 4, c = i & 15;
        int gr = row0 + r;
        int ok = (gr < n) ? 16 : 0;
        int grc = (gr < n) ? gr : 0;
        cp16(sAu + r * ASTB + c * 16, Asrc + ((size_t)grc * 16 + c), ok);
        cp16(sBu + r * ASTB + c * 16, Bsrc + i, 16);
    }
    cp_commit_wait0();
    __syncthreads();

    int wm = warp >> 1;            // 0..3  (M)
    int wn = warp & 1;             // 0..1  (N)
    int m0 = wm * 32;
    int n0 = wn * 64;

    // A fragment base: bit3(lane)->row+8, bit4(lane)->k+16B
    uint32_t a_base = sAu + (m0 + (lane & 7) + ((lane & 8) ? 8 : 0)) * ASTB
                          + ((lane & 16) ? 16 : 0);
    // B fragment base: bit3->k+16B, bit4->n-row+8
    uint32_t b_base = sBu + (n0 + (lane & 7) + ((lane & 16) ? 8 : 0)) * ASTB
                          + ((lane & 8) ? 16 : 0);

    float acc[2][8][4];
#pragma unroll
    for (int mt = 0; mt < 2; mt++)
#pragma unroll
        for (int j = 0; j < 8; j++)
#pragma unroll
            for (int q = 0; q < 4; q++) acc[mt][j][q] = 0.f;

#pragma unroll
    for (int ks = 0; ks < 8; ks++) {
        uint32_t a[2][4];
#pragma unroll
        for (int mt = 0; mt < 2; mt++)
            ldsm_x4(a[mt][0], a[mt][1], a[mt][2], a[mt][3],
                    a_base + mt * 16 * ASTB + ks * 32);
#pragma unroll
        for (int jj = 0; jj < 4; jj++) {
            uint32_t b0, b1, b2, b3;
            ldsm_x4(b0, b1, b2, b3, b_base + jj * 16 * ASTB + ks * 32);
#pragma unroll
            for (int mt = 0; mt < 2; mt++) {
                mma16816(acc[mt][2 * jj],     a[mt][0], a[mt][1], a[mt][2], a[mt][3], b0, b1);
                mma16816(acc[mt][2 * jj + 1], a[mt][0], a[mt][1], a[mt][2], a[mt][3], b2, b3);
            }
        }
    }
    __syncthreads();   // all warps done reading smem A/B

    // epilogue: scale, fp16, stmatrix into reused sA, coalesced stores
    float ns0[2], ns1[2];
#pragma unroll
    for (int mt = 0; mt < 2; mt++) {
        int mr0 = row0 + m0 + mt * 16 + (lane >> 2);
        int mr1 = mr0 + 8;
        ns0[mt] = (mr0 < n) ? rsqrtf((float)max(g_cnt_src[mr0], 1)) : 0.f;
        ns1[mt] = (mr1 < n) ? rsqrtf((float)max(g_cnt_src[mr1], 1)) : 0.f;
    }
#pragma unroll
    for (int mt = 0; mt < 2; mt++) {
        uint32_t st_base = sAu
            + (m0 + mt * 16 + (lane & 7) + ((lane & 8) ? 8 : 0)) * ASTB
            + n0 * 2 + ((lane & 16) ? 16 : 0);
#pragma unroll
        for (int jj = 0; jj < 4; jj++) {
            __half2 t0lo = __floats2half2_rn(acc[mt][2*jj][0] * ns0[mt],
                                             acc[mt][2*jj][1] * ns0[mt]);
            __half2 t0hi = __floats2half2_rn(acc[mt][2*jj][2] * ns1[mt],
                                             acc[mt][2*jj][3] * ns1[mt]);
            __half2 t1lo = __floats2half2_rn(acc[mt][2*jj+1][0] * ns0[mt],
                                             acc[mt][2*jj+1][1] * ns0[mt]);
            __half2 t1hi = __floats2half2_rn(acc[mt][2*jj+1][2] * ns1[mt],
                                             acc[mt][2*jj+1][3] * ns1[mt]);
            stsm_x4(st_base + jj * 32,
                    *reinterpret_cast<uint32_t*>(&t0lo),
                    *reinterpret_cast<uint32_t*>(&t0hi),
                    *reinterpret_cast<uint32_t*>(&t1lo),
                    *reinterpret_cast<uint32_t*>(&t1hi));
        }
    }
    __syncthreads();

    for (int i = tid; i < 2048; i += 256) {
        int r = i >> 4, c = i & 15;
        int gr = row0 + r;
        if (gr < n)
            reinterpret_cast<uint4*>(g_hw)[(size_t)gr * 16 + c] =
                *reinterpret_cast<uint4*>(sA + r * ASTB + c * 16);
    }
}

// ---------------- edge aggregation: h = relu(norm_dst ⊙ (A @ hw) + b) --------
// warp per dst node; lane owns 4 dims (8B fp16 load), fp32 accumulate, unroll 8.
__global__ void __launch_bounds__(256) k_agg(const float* __restrict__ bias, int n) {
    int warp = (blockIdx.x * blockDim.x + threadIdx.x) >> 5;
    int lane = threadIdx.x & 31;
    if (warp >= n) return;

    int beg = g_row_ptr[warp];
    int end = g_row_ptr[warp + 1];

    const uint2* hw2 = reinterpret_cast<const uint2*>(g_hw);
    float ax0 = 0.f, ay0 = 0.f, az0 = 0.f, aw0 = 0.f;
    float ax1 = 0.f, ay1 = 0.f, az1 = 0.f, aw1 = 0.f;

    int e = beg;
    for (; e + 7 < end; e += 8) {
        int s[8];
#pragma unroll
        for (int j = 0; j < 8; j++) s[j] = g_csr[e + j];
        uint2 v[8];
#pragma unroll
        for (int j = 0; j < 8; j++) v[j] = hw2[(size_t)s[j] * 32 + lane];
#pragma unroll
        for (int j = 0; j < 8; j++) {
            float2 fa = __half22float2(*reinterpret_cast<__half2*>(&v[j].x));
            float2 fb = __half22float2(*reinterpret_cast<__half2*>(&v[j].y));
            if (j & 1) { ax1 += fa.x; ay1 += fa.y; az1 += fb.x; aw1 += fb.y; }
            else       { ax0 += fa.x; ay0 += fa.y; az0 += fb.x; aw0 += fb.y; }
        }
    }
    for (; e < end; ++e) {
        uint2 v = hw2[(size_t)g_csr[e] * 32 + lane];
        float2 fa = __half22float2(*reinterpret_cast<__half2*>(&v.x));
        float2 fb = __half22float2(*reinterpret_cast<__half2*>(&v.y));
        ax0 += fa.x; ay0 += fa.y; az0 += fb.x; aw0 += fb.y;
    }

    float nd = g_norm_dst[warp];
    float4 bb = reinterpret_cast<const float4*>(bias)[lane];
    float ox = fmaxf(fmaf(ax0 + ax1, nd, bb.x), 0.f);
    float oy = fmaxf(fmaf(ay0 + ay1, nd, bb.y), 0.f);
    float oz = fmaxf(fmaf(az0 + az1, nd, bb.z), 0.f);
    float ow = fmaxf(fmaf(aw0 + aw1, nd, bb.w), 0.f);
    __half2 p0 = __floats2half2_rn(ox, oy);
    __half2 p1 = __floats2half2_rn(oz, ow);
    uint2 o;
    o.x = *reinterpret_cast<uint32_t*>(&p0);
    o.y = *reinterpret_cast<uint32_t*>(&p1);
    reinterpret_cast<uint2*>(g_hf)[(size_t)warp * 32 + lane] = o;
}

// ---------------- per-graph max readout (graph_ids sorted) -------------------
__global__ void k_readout(const int* __restrict__ gids, float* __restrict__ out, int n) {
    __shared__ int sg[512];
    int n0 = blockIdx.x * 512;
    int cnt = min(512, n - n0);
    if (cnt <= 0) return;
    for (int i = threadIdx.x; i < cnt; i += 128) sg[i] = gids[n0 + i];
    __syncthreads();

    int d = threadIdx.x;
    int cur = sg[0];
    float m = 0.f;
    for (int i = 0; i < cnt; i++) {
        int g = sg[i];
        if (g != cur) {
            atomicMax(reinterpret_cast<int*>(&out[cur * DIMV + d]), __float_as_int(m));
            m = 0.f;
            cur = g;
        }
        m = fmaxf(m, __half2float(g_hf[(size_t)(n0 + i) * DIMV + d]));
    }
    atomicMax(reinterpret_cast<int*>(&out[cur * DIMV + d]), __float_as_int(m));
}

// ---------------- launch ------------------------------------------------------
extern "C" void kernel_launch(void* const* d_in, const int* in_sizes, int n_in,
                              void* d_out, int out_size) {
    const int*   feat_id = (const int*)  d_in[0];
    const int*   src     = (const int*)  d_in[1];
    const int*   dst     = (const int*)  d_in[2];
    const int*   gids    = (const int*)  d_in[3];
    const float* emb     = (const float*)d_in[4];
    const float* W       = (const float*)d_in[5];
    const float* b       = (const float*)d_in[6];
    float*       out     = (float*)d_out;

    int N = in_sizes[0];
    int E = in_sizes[1];
    int LAYERS = in_sizes[6] / DIMV;

    const int T = 256;
    int nbN   = (N + T - 1) / T;
    int nbE4  = ((E + 3) / 4 + T - 1) / T;
    int nbSc  = (N + SCAN_B - 1) / SCAN_B;
    int nbOut = (out_size + T - 1) / T;

    cudaFuncSetAttribute(k_gemm_hmma, cudaFuncAttributeMaxDynamicSharedMemorySize, SM_GEMM);

    int tiles = (N + 127) / 128;
    int aggBlocks = (N + 7) / 8;   // 8 warps/block, warp per node

    __half* wt_dev = nullptr;
    cudaGetSymbolAddress((void**)&wt_dev, g_wt);

    // ordered so k_gemm_hmma is launch #3 (ncu capture slot)
    k_prep<<<nbN + LAYERS + nbOut, T>>>(W, nbN, N, LAYERS, out, out_size);  // 0
    k_hist<<<nbE4, T>>>(src, dst, E);                                       // 1
    k_embed<<<(N * 16 + T - 1) / T, T>>>(feat_id, emb, N);                  // 2
    k_gemm_hmma<<<tiles, 256, SM_GEMM>>>(wt_dev, N);                        // 3 <- profiled

    k_scan1<<<nbSc, SCAN_B>>>(N);
    k_scan2<<<1, SCAN_B>>>(nbSc);
    k_scan3<<<nbN, T>>>(N, E);
    k_fill<<<nbE4, T>>>(src, dst, E);

    k_agg<<<aggBlocks, 256>>>(b, N);
    for (int l = 1; l < LAYERS; l++) {
        k_gemm_hmma<<<tiles, 256, SM_GEMM>>>(wt_dev + (size_t)l * DIMV * DIMV, N);
        k_agg<<<aggBlocks, 256>>>(b + (size_t)l * DIMV, N);
    }

    k_readout<<<(N + 511) / 512, 128>>>(gids, out, N);
}

// round 8
// speedup vs baseline: 2.2473x; 1.0272x over previous
#include <cuda_runtime.h>
#include <cuda_bf16.h>
#include <cuda_fp16.h>
#include <cstdint>

#define MAXN 100000
#define MAXE 1600000
#define DIMV 128
#define SCAN_B 1024
#define MAXL 8
#define ASTH 136           // padded smem stride in halves
#define ASTB 272           // padded smem stride in bytes
#define GRIDP 296          // persistent GEMM grid (2 blocks/SM x 148)

// ---------------- scratch (device globals; no allocation allowed) -------------
__device__ __align__(256) __half g_hf[MAXN * DIMV];        // node features (fp16)
__device__ __align__(256) __half g_hw[MAXN * DIMV];        // h @ W * norm_src (fp16)
__device__ __align__(256) __half g_wt[MAXL * DIMV * DIMV]; // W^T per layer (fp16)
__device__ int    g_csr[MAXE];
__device__ int    g_row_ptr[MAXN + 1];
__device__ int    g_cursor[MAXN];
__device__ int    g_cnt_src[MAXN];
__device__ int    g_cnt_dst[MAXN];
__device__ float  g_norm_dst[MAXN];
__device__ int    g_spine[256];

// ---------------- PTX helpers (base-PTX: ldmatrix/stmatrix/mma/cp.async) ------
__device__ __forceinline__ uint32_t smem_u32(const void* p) {
    uint32_t a;
    asm("{ .reg .u64 t; cvta.to.shared.u64 t, %1; cvt.u32.u64 %0, t; }" : "=r"(a) : "l"(p));
    return a;
}
__device__ __forceinline__ void ldsm_x4(uint32_t& r0, uint32_t& r1, uint32_t& r2,
                                        uint32_t& r3, uint32_t addr) {
    asm volatile("ldmatrix.sync.aligned.m8n8.x4.shared.b16 {%0,%1,%2,%3}, [%4];"
                 : "=r"(r0), "=r"(r1), "=r"(r2), "=r"(r3) : "r"(addr));
}
__device__ __forceinline__ void stsm_x4(uint32_t addr, uint32_t r0, uint32_t r1,
                                        uint32_t r2, uint32_t r3) {
    asm volatile("stmatrix.sync.aligned.m8n8.x4.shared.b16 [%0], {%1,%2,%3,%4};"
                 :: "r"(addr), "r"(r0), "r"(r1), "r"(r2), "r"(r3) : "memory");
}
__device__ __forceinline__ void mma16816(float* c, uint32_t a0, uint32_t a1,
                                         uint32_t a2, uint32_t a3,
                                         uint32_t b0, uint32_t b1) {
    asm volatile("mma.sync.aligned.m16n8k16.row.col.f32.f16.f16.f32 "
                 "{%0,%1,%2,%3}, {%4,%5,%6,%7}, {%8,%9}, {%0,%1,%2,%3};"
                 : "+f"(c[0]), "+f"(c[1]), "+f"(c[2]), "+f"(c[3])
                 : "r"(a0), "r"(a1), "r"(a2), "r"(a3), "r"(b0), "r"(b1));
}
__device__ __forceinline__ void cp16(uint32_t daddr, const void* gaddr, int srcbytes) {
    asm volatile("cp.async.cg.shared.global [%0], [%1], 16, %2;"
                 :: "r"(daddr), "l"(gaddr), "r"(srcbytes) : "memory");
}
__device__ __forceinline__ void cp_commit() {
    asm volatile("cp.async.commit_group;" ::: "memory");
}
__device__ __forceinline__ void cp_wait0() {
    asm volatile("cp.async.wait_group 0;" ::: "memory");
}

// ---------------- prep: zero counters + transpose W + zero out ----------------
__global__ void k_prep(const float* __restrict__ W, int nbN, int n, int layers,
                       float* __restrict__ out, int out_n) {
    int b = blockIdx.x;
    if (b < nbN) {
        int i = b * 256 + threadIdx.x;
        if (i < n) { g_cnt_src[i] = 0; g_cnt_dst[i] = 0; }
    } else if (b < nbN + layers) {
        int l = b - nbN;
        const float* Wl = W + (size_t)l * DIMV * DIMV;
        __half* Wt = g_wt + (size_t)l * DIMV * DIMV;
        for (int i = threadIdx.x; i < DIMV * DIMV; i += 256) {
            int nr = i >> 7, k = i & 127;
            Wt[nr * DIMV + k] = __float2half(Wl[k * DIMV + nr]);
        }
    } else {
        int i = (b - nbN - layers) * 256 + threadIdx.x;
        if (i < out_n) out[i] = 0.0f;
    }
}

// ---------------- degree histograms (4 edges/thread) --------------------------
__global__ void k_hist(const int* __restrict__ src, const int* __restrict__ dst, int E) {
    int q = blockIdx.x * blockDim.x + threadIdx.x;
    int e0 = q * 4;
    if (e0 + 3 < E) {
        int4 s = *reinterpret_cast<const int4*>(src + e0);
        int4 d = *reinterpret_cast<const int4*>(dst + e0);
        atomicAdd(&g_cnt_src[s.x], 1); atomicAdd(&g_cnt_src[s.y], 1);
        atomicAdd(&g_cnt_src[s.z], 1); atomicAdd(&g_cnt_src[s.w], 1);
        atomicAdd(&g_cnt_dst[d.x], 1); atomicAdd(&g_cnt_dst[d.y], 1);
        atomicAdd(&g_cnt_dst[d.z], 1); atomicAdd(&g_cnt_dst[d.w], 1);
    } else {
        for (int e = e0; e < E; ++e) {
            atomicAdd(&g_cnt_src[src[e]], 1);
            atomicAdd(&g_cnt_dst[dst[e]], 1);
        }
    }
}

// ---------------- scan of in-degree counts -> row_ptr (+ norm_dst) ------------
__global__ void k_scan1(int n) {
    __shared__ int s[SCAN_B];
    int i = blockIdx.x * SCAN_B + threadIdx.x;
    int v = (i < n) ? g_cnt_dst[i] : 0;
    if (i < n) g_norm_dst[i] = rsqrtf((float)max(v, 1));
    s[threadIdx.x] = v;
    __syncthreads();
    for (int off = 1; off < SCAN_B; off <<= 1) {
        int t = (threadIdx.x >= off) ? s[threadIdx.x - off] : 0;
        __syncthreads();
        s[threadIdx.x] += t;
        __syncthreads();
    }
    if (i < n) g_row_ptr[i] = s[threadIdx.x] - v;
    if (threadIdx.x == SCAN_B - 1) g_spine[blockIdx.x] = s[SCAN_B - 1];
}

__global__ void k_scan2(int nb) {
    __shared__ int s[SCAN_B];
    int v = (threadIdx.x < nb) ? g_spine[threadIdx.x] : 0;
    s[threadIdx.x] = v;
    __syncthreads();
    for (int off = 1; off < SCAN_B; off <<= 1) {
        int t = (threadIdx.x >= off) ? s[threadIdx.x - off] : 0;
        __syncthreads();
        s[threadIdx.x] += t;
        __syncthreads();
    }
    if (threadIdx.x < nb) g_spine[threadIdx.x] = s[threadIdx.x] - v;
}

__global__ void k_scan3(int n, int E) {
    int i = blockIdx.x * blockDim.x + threadIdx.x;
    if (i < n) {
        int r = g_row_ptr[i] + g_spine[i / SCAN_B];
        g_row_ptr[i] = r;
        g_cursor[i]  = r;
    }
    if (i == 0) g_row_ptr[n] = E;
}

// ---------------- CSR fill (counting sort by dst, 4 edges/thread) -------------
__global__ void k_fill(const int* __restrict__ src, const int* __restrict__ dst, int E) {
    int q = blockIdx.x * blockDim.x + threadIdx.x;
    int e0 = q * 4;
    if (e0 + 3 < E) {
        int4 s = *reinterpret_cast<const int4*>(src + e0);
        int4 d = *reinterpret_cast<const int4*>(dst + e0);
        g_csr[atomicAdd(&g_cursor[d.x], 1)] = s.x;
        g_csr[atomicAdd(&g_cursor[d.y], 1)] = s.y;
        g_csr[atomicAdd(&g_cursor[d.z], 1)] = s.z;
        g_csr[atomicAdd(&g_cursor[d.w], 1)] = s.w;
    } else {
        for (int e = e0; e < E; ++e)
            g_csr[atomicAdd(&g_cursor[dst[e]], 1)] = src[e];
    }
}

// ---------------- embedding gather -> fp16 h ---------------------------------
__global__ void k_embed(const int* __restrict__ feat_id, const float* __restrict__ emb, int n) {
    int idx = blockIdx.x * blockDim.x + threadIdx.x;
    if (idx < n * 16) {
        int node = idx >> 4;
        int c    = idx & 15;
        const float4* e = reinterpret_cast<const float4*>(emb) + (size_t)feat_id[node] * 32 + c * 2;
        float4 a = e[0], b = e[1];
        __half2 h0 = __floats2half2_rn(a.x, a.y);
        __half2 h1 = __floats2half2_rn(a.z, a.w);
        __half2 h2 = __floats2half2_rn(b.x, b.y);
        __half2 h3 = __floats2half2_rn(b.z, b.w);
        uint4 v;
        v.x = *reinterpret_cast<uint32_t*>(&h0);
        v.y = *reinterpret_cast<uint32_t*>(&h1);
        v.z = *reinterpret_cast<uint32_t*>(&h2);
        v.w = *reinterpret_cast<uint32_t*>(&h3);
        reinterpret_cast<uint4*>(g_hf)[idx] = v;
    }
}

// ---------------- persistent HMMA GEMM: hw = norm_src ⊙ (h @ W) --------------
// Grid = GRIDP blocks (2/SM). B = W^T resident in smem per block; A tiles
// double-buffered with cp.async prefetch overlapping compute.
#define SMO_B  0
#define SMO_A0 34816
#define SMO_A1 69632
#define SM_GEMM 104448

__global__ void __launch_bounds__(256) k_gemm_hmma(const __half* __restrict__ Wt,
                                                   int n, int tiles) {
    extern __shared__ char sm[];
    uint32_t sBu  = smem_u32(sm) + SMO_B;
    uint32_t sAu[2] = { smem_u32(sm) + SMO_A0, smem_u32(sm) + SMO_A1 };
    int tid = threadIdx.x, warp = tid >> 5, lane = tid & 31;

    int t0 = blockIdx.x;
    if (t0 >= tiles) return;

    const uint4* Asrc = reinterpret_cast<const uint4*>(g_hf);
    const uint4* Bsrc = reinterpret_cast<const uint4*>(Wt);

    // prologue: B + first A tile
    for (int i = tid; i < 2048; i += 256) {
        int r = i >> 4, c = i & 15;
        cp16(sBu + r * ASTB + c * 16, Bsrc + i, 16);
    }
    {
        int row0 = t0 * 128;
        for (int i = tid; i < 2048; i += 256) {
            int r = i >> 4, c = i & 15;
            int gr = row0 + r;
            int ok = (gr < n) ? 16 : 0;
            int grc = (gr < n) ? gr : 0;
            cp16(sAu[0] + r * ASTB + c * 16, Asrc + ((size_t)grc * 16 + c), ok);
        }
    }
    cp_commit();
    cp_wait0();
    __syncthreads();

    int wm = warp >> 1, wn = warp & 1;
    int m0 = wm * 32, nn0 = wn * 64;

    uint32_t a_off = (m0 + (lane & 7) + ((lane & 8) ? 8 : 0)) * ASTB
                   + ((lane & 16) ? 16 : 0);
    uint32_t b_base = sBu + (nn0 + (lane & 7) + ((lane & 16) ? 8 : 0)) * ASTB
                          + ((lane & 8) ? 16 : 0);

    int cur = 0;
    for (int t = t0; t < tiles; t += GRIDP) {
        int row0 = t * 128;
        int tnext = t + GRIDP;

        // prefetch next A tile into other buffer
        if (tnext < tiles) {
            int nrow0 = tnext * 128;
            for (int i = tid; i < 2048; i += 256) {
                int r = i >> 4, c = i & 15;
                int gr = nrow0 + r;
                int ok = (gr < n) ? 16 : 0;
                int grc = (gr < n) ? gr : 0;
                cp16(sAu[cur ^ 1] + r * ASTB + c * 16, Asrc + ((size_t)grc * 16 + c), ok);
            }
            cp_commit();
        }

        uint32_t a_base = sAu[cur] + a_off;

        float acc[2][8][4];
#pragma unroll
        for (int mt = 0; mt < 2; mt++)
#pragma unroll
            for (int j = 0; j < 8; j++)
#pragma unroll
                for (int q = 0; q < 4; q++) acc[mt][j][q] = 0.f;

#pragma unroll
        for (int ks = 0; ks < 8; ks++) {
            uint32_t a[2][4];
#pragma unroll
            for (int mt = 0; mt < 2; mt++)
                ldsm_x4(a[mt][0], a[mt][1], a[mt][2], a[mt][3],
                        a_base + mt * 16 * ASTB + ks * 32);
#pragma unroll
            for (int jj = 0; jj < 4; jj++) {
                uint32_t b0, b1, b2, b3;
                ldsm_x4(b0, b1, b2, b3, b_base + jj * 16 * ASTB + ks * 32);
#pragma unroll
                for (int mt = 0; mt < 2; mt++) {
                    mma16816(acc[mt][2 * jj],     a[mt][0], a[mt][1], a[mt][2], a[mt][3], b0, b1);
                    mma16816(acc[mt][2 * jj + 1], a[mt][0], a[mt][1], a[mt][2], a[mt][3], b2, b3);
                }
            }
        }
        __syncthreads();   // done reading A[cur]

        // epilogue into A[cur] smem, then coalesced stores
        float ns0[2], ns1[2];
#pragma unroll
        for (int mt = 0; mt < 2; mt++) {
            int mr0 = row0 + m0 + mt * 16 + (lane >> 2);
            int mr1 = mr0 + 8;
            ns0[mt] = (mr0 < n) ? rsqrtf((float)max(g_cnt_src[mr0], 1)) : 0.f;
            ns1[mt] = (mr1 < n) ? rsqrtf((float)max(g_cnt_src[mr1], 1)) : 0.f;
        }
#pragma unroll
        for (int mt = 0; mt < 2; mt++) {
            uint32_t st_base = sAu[cur]
                + (m0 + mt * 16 + (lane & 7) + ((lane & 8) ? 8 : 0)) * ASTB
                + nn0 * 2 + ((lane & 16) ? 16 : 0);
#pragma unroll
            for (int jj = 0; jj < 4; jj++) {
                __half2 t0lo = __floats2half2_rn(acc[mt][2*jj][0] * ns0[mt],
                                                 acc[mt][2*jj][1] * ns0[mt]);
                __half2 t0hi = __floats2half2_rn(acc[mt][2*jj][2] * ns1[mt],
                                                 acc[mt][2*jj][3] * ns1[mt]);
                __half2 t1lo = __floats2half2_rn(acc[mt][2*jj+1][0] * ns0[mt],
                                                 acc[mt][2*jj+1][1] * ns0[mt]);
                __half2 t1hi = __floats2half2_rn(acc[mt][2*jj+1][2] * ns1[mt],
                                                 acc[mt][2*jj+1][3] * ns1[mt]);
                stsm_x4(st_base + jj * 32,
                        *reinterpret_cast<uint32_t*>(&t0lo),
                        *reinterpret_cast<uint32_t*>(&t0hi),
                        *reinterpret_cast<uint32_t*>(&t1lo),
                        *reinterpret_cast<uint32_t*>(&t1hi));
            }
        }
        __syncthreads();

        char* sAc = sm + (cur ? SMO_A1 : SMO_A0);
        for (int i = tid; i < 2048; i += 256) {
            int r = i >> 4, c = i & 15;
            int gr = row0 + r;
            if (gr < n)
                reinterpret_cast<uint4*>(g_hw)[(size_t)gr * 16 + c] =
                    *reinterpret_cast<uint4*>(sAc + r * ASTB + c * 16);
        }

        if (tnext < tiles) {
            cp_wait0();
            __syncthreads();   // A[next] ready; also orders smem reads before reuse
        }
        cur ^= 1;
    }
}

// ---------------- edge aggregation: h = relu(norm_dst ⊙ (A @ hw) + b) --------
// half-warp per dst node; lane owns 8 dims (16B fp16 LDG.128), unroll 8.
// row = 128 halves = 16 uint4; l16 in [0,16) indexes them.
__global__ void __launch_bounds__(256) k_agg(const float* __restrict__ bias, int n) {
    int gw   = (blockIdx.x * blockDim.x + threadIdx.x) >> 5;
    int lane = threadIdx.x & 31;
    int node = gw * 2 + (lane >> 4);
    int l16  = lane & 15;
    if (node >= n) return;

    int beg = g_row_ptr[node];
    int end = g_row_ptr[node + 1];

    const uint4* hw4 = reinterpret_cast<const uint4*>(g_hw);   // row = 16 uint4
    float a0 = 0.f, a1 = 0.f, a2 = 0.f, a3 = 0.f;
    float a4 = 0.f, a5 = 0.f, a6 = 0.f, a7 = 0.f;

    int e = beg;
    for (; e + 7 < end; e += 8) {
        int s[8];
#pragma unroll
        for (int j = 0; j < 8; j++) s[j] = g_csr[e + j];
        uint4 v[8];
#pragma unroll
        for (int j = 0; j < 8; j++) v[j] = hw4[(size_t)s[j] * 16 + l16];
#pragma unroll
        for (int j = 0; j < 8; j++) {
            float2 f0 = __half22float2(*reinterpret_cast<__half2*>(&v[j].x));
            float2 f1 = __half22float2(*reinterpret_cast<__half2*>(&v[j].y));
            float2 f2 = __half22float2(*reinterpret_cast<__half2*>(&v[j].z));
            float2 f3 = __half22float2(*reinterpret_cast<__half2*>(&v[j].w));
            a0 += f0.x; a1 += f0.y; a2 += f1.x; a3 += f1.y;
            a4 += f2.x; a5 += f2.y; a6 += f3.x; a7 += f3.y;
        }
    }
    for (; e < end; ++e) {
        uint4 v = hw4[(size_t)g_csr[e] * 16 + l16];
        float2 f0 = __half22float2(*reinterpret_cast<__half2*>(&v.x));
        float2 f1 = __half22float2(*reinterpret_cast<__half2*>(&v.y));
        float2 f2 = __half22float2(*reinterpret_cast<__half2*>(&v.z));
        float2 f3 = __half22float2(*reinterpret_cast<__half2*>(&v.w));
        a0 += f0.x; a1 += f0.y; a2 += f1.x; a3 += f1.y;
        a4 += f2.x; a5 += f2.y; a6 += f3.x; a7 += f3.y;
    }

    float nd = g_norm_dst[node];
    float4 bb0 = reinterpret_cast<const float4*>(bias)[l16 * 2];
    float4 bb1 = reinterpret_cast<const float4*>(bias)[l16 * 2 + 1];
    __half2 p0 = __floats2half2_rn(fmaxf(fmaf(a0, nd, bb0.x), 0.f),
                                   fmaxf(fmaf(a1, nd, bb0.y), 0.f));
    __half2 p1 = __floats2half2_rn(fmaxf(fmaf(a2, nd, bb0.z), 0.f),
                                   fmaxf(fmaf(a3, nd, bb0.w), 0.f));
    __half2 p2 = __floats2half2_rn(fmaxf(fmaf(a4, nd, bb1.x), 0.f),
                                   fmaxf(fmaf(a5, nd, bb1.y), 0.f));
    __half2 p3 = __floats2half2_rn(fmaxf(fmaf(a6, nd, bb1.z), 0.f),
                                   fmaxf(fmaf(a7, nd, bb1.w), 0.f));
    uint4 o;
    o.x = *reinterpret_cast<uint32_t*>(&p0);
    o.y = *reinterpret_cast<uint32_t*>(&p1);
    o.z = *reinterpret_cast<uint32_t*>(&p2);
    o.w = *reinterpret_cast<uint32_t*>(&p3);
    reinterpret_cast<uint4*>(g_hf)[(size_t)node * 16 + l16] = o;
}

// ---------------- per-graph max readout (graph_ids sorted) -------------------
__global__ void k_readout(const int* __restrict__ gids, float* __restrict__ out, int n) {
    __shared__ int sg[512];
    int n0 = blockIdx.x * 512;
    int cnt = min(512, n - n0);
    if (cnt <= 0) return;
    for (int i = threadIdx.x; i < cnt; i += 128) sg[i] = gids[n0 + i];
    __syncthreads();

    int d = threadIdx.x;
    int cur = sg[0];
    float m = 0.f;
    for (int i = 0; i < cnt; i++) {
        int g = sg[i];
        if (g != cur) {
            atomicMax(reinterpret_cast<int*>(&out[cur * DIMV + d]), __float_as_int(m));
            m = 0.f;
            cur = g;
        }
        m = fmaxf(m, __half2float(g_hf[(size_t)(n0 + i) * DIMV + d]));
    }
    atomicMax(reinterpret_cast<int*>(&out[cur * DIMV + d]), __float_as_int(m));
}

// ---------------- launch ------------------------------------------------------
extern "C" void kernel_launch(void* const* d_in, const int* in_sizes, int n_in,
                              void* d_out, int out_size) {
    const int*   feat_id = (const int*)  d_in[0];
    const int*   src     = (const int*)  d_in[1];
    const int*   dst     = (const int*)  d_in[2];
    const int*   gids    = (const int*)  d_in[3];
    const float* emb     = (const float*)d_in[4];
    const float* W       = (const float*)d_in[5];
    const float* b       = (const float*)d_in[6];
    float*       out     = (float*)d_out;

    int N = in_sizes[0];
    int E = in_sizes[1];
    int LAYERS = in_sizes[6] / DIMV;

    const int T = 256;
    int nbN   = (N + T - 1) / T;
    int nbE4  = ((E + 3) / 4 + T - 1) / T;
    int nbSc  = (N + SCAN_B - 1) / SCAN_B;
    int nbOut = (out_size + T - 1) / T;

    cudaFuncSetAttribute(k_gemm_hmma, cudaFuncAttributeMaxDynamicSharedMemorySize, SM_GEMM);

    int tiles = (N + 127) / 128;
    int gemmGrid = (tiles < GRIDP) ? tiles : GRIDP;
    int aggBlocks = ((N + 1) / 2 + 7) / 8;   // 8 warps/block, 2 nodes/warp

    __half* wt_dev = nullptr;
    cudaGetSymbolAddress((void**)&wt_dev, g_wt);

    // ordered so k_gemm_hmma is launch #3 (ncu capture slot)
    k_prep<<<nbN + LAYERS + nbOut, T>>>(W, nbN, N, LAYERS, out, out_size);  // 0
    k_hist<<<nbE4, T>>>(src, dst, E);                                       // 1
    k_embed<<<(N * 16 + T - 1) / T, T>>>(feat_id, emb, N);                  // 2
    k_gemm_hmma<<<gemmGrid, 256, SM_GEMM>>>(wt_dev, N, tiles);              // 3 <- profiled

    k_scan1<<<nbSc, SCAN_B>>>(N);
    k_scan2<<<1, SCAN_B>>>(nbSc);
    k_scan3<<<nbN, T>>>(N, E);
    k_fill<<<nbE4, T>>>(src, dst, E);

    k_agg<<<aggBlocks, 256>>>(b, N);
    for (int l = 1; l < LAYERS; l++) {
        k_gemm_hmma<<<gemmGrid, 256, SM_GEMM>>>(wt_dev + (size_t)l * DIMV * DIMV, N, tiles);
        k_agg<<<aggBlocks, 256>>>(b + (size_t)l * DIMV, N);
    }

    k_readout<<<(N + 511) / 512, 128>>>(gids, out, N);
}

// round 9
// speedup vs baseline: 3.2252x; 1.4352x over previous
#include <cuda_runtime.h>
#include <cuda_bf16.h>
#include <cuda_fp16.h>
#include <cstdint>

#define MAXN 100000
#define MAXE 1600000
#define DIMV 128
#define SCAN_B 1024
#define MAXL 8
#define ASTH 136           // padded smem stride in halves
#define ASTB 272           // padded smem stride in bytes
#define GRIDP 296          // persistent GEMM grid (2 blocks/SM x 148)
#define RD_SLOTS 16        // per-block graph slots in fused agg+readout

// ---------------- scratch (device globals; no allocation allowed) -------------
__device__ __align__(256) __half g_hf[MAXN * DIMV];        // node features (fp16)
__device__ __align__(256) __half g_hw[MAXN * DIMV];        // h @ W * norm_src (fp16)
__device__ __align__(256) __half g_wt[MAXL * DIMV * DIMV]; // W^T per layer (fp16)
__device__ int    g_csr[MAXE];
__device__ int    g_row_ptr[MAXN + 1];
__device__ int    g_cursor[MAXN];
__device__ int    g_cnt_src[MAXN];
__device__ int    g_cnt_dst[MAXN];
__device__ float  g_norm_dst[MAXN];
__device__ int    g_spine[256];

// ---------------- side stream + events (created at load, before baseline) -----
struct StreamInit {
    cudaStream_t s2;
    cudaEvent_t evA, evB, evC;
    StreamInit() {
        cudaStreamCreateWithFlags(&s2, cudaStreamNonBlocking);
        cudaEventCreateWithFlags(&evA, cudaEventDisableTiming);
        cudaEventCreateWithFlags(&evB, cudaEventDisableTiming);
        cudaEventCreateWithFlags(&evC, cudaEventDisableTiming);
    }
};
static StreamInit g_si;

// ---------------- PTX helpers (base-PTX: ldmatrix/stmatrix/mma/cp.async) ------
__device__ __forceinline__ uint32_t smem_u32(const void* p) {
    uint32_t a;
    asm("{ .reg .u64 t; cvta.to.shared.u64 t, %1; cvt.u32.u64 %0, t; }" : "=r"(a) : "l"(p));
    return a;
}
__device__ __forceinline__ void ldsm_x4(uint32_t& r0, uint32_t& r1, uint32_t& r2,
                                        uint32_t& r3, uint32_t addr) {
    asm volatile("ldmatrix.sync.aligned.m8n8.x4.shared.b16 {%0,%1,%2,%3}, [%4];"
                 : "=r"(r0), "=r"(r1), "=r"(r2), "=r"(r3) : "r"(addr));
}
__device__ __forceinline__ void stsm_x4(uint32_t addr, uint32_t r0, uint32_t r1,
                                        uint32_t r2, uint32_t r3) {
    asm volatile("stmatrix.sync.aligned.m8n8.x4.shared.b16 [%0], {%1,%2,%3,%4};"
                 :: "r"(addr), "r"(r0), "r"(r1), "r"(r2), "r"(r3) : "memory");
}
__device__ __forceinline__ void mma16816(float* c, uint32_t a0, uint32_t a1,
                                         uint32_t a2, uint32_t a3,
                                         uint32_t b0, uint32_t b1) {
    asm volatile("mma.sync.aligned.m16n8k16.row.col.f32.f16.f16.f32 "
                 "{%0,%1,%2,%3}, {%4,%5,%6,%7}, {%8,%9}, {%0,%1,%2,%3};"
                 : "+f"(c[0]), "+f"(c[1]), "+f"(c[2]), "+f"(c[3])
                 : "r"(a0), "r"(a1), "r"(a2), "r"(a3), "r"(b0), "r"(b1));
}
__device__ __forceinline__ void cp16(uint32_t daddr, const void* gaddr, int srcbytes) {
    asm volatile("cp.async.cg.shared.global [%0], [%1], 16, %2;"
                 :: "r"(daddr), "l"(gaddr), "r"(srcbytes) : "memory");
}
__device__ __forceinline__ void cp_commit() {
    asm volatile("cp.async.commit_group;" ::: "memory");
}
__device__ __forceinline__ void cp_wait0() {
    asm volatile("cp.async.wait_group 0;" ::: "memory");
}

// ---------------- prep: zero counters + transpose W + zero out ----------------
__global__ void k_prep(const float* __restrict__ W, int nbN, int n, int layers,
                       float* __restrict__ out, int out_n) {
    int b = blockIdx.x;
    if (b < nbN) {
        int i = b * 256 + threadIdx.x;
        if (i < n) { g_cnt_src[i] = 0; g_cnt_dst[i] = 0; }
    } else if (b < nbN + layers) {
        int l = b - nbN;
        const float* Wl = W + (size_t)l * DIMV * DIMV;
        __half* Wt = g_wt + (size_t)l * DIMV * DIMV;
        for (int i = threadIdx.x; i < DIMV * DIMV; i += 256) {
            int nr = i >> 7, k = i & 127;
            Wt[nr * DIMV + k] = __float2half(Wl[k * DIMV + nr]);
        }
    } else {
        int i = (b - nbN - layers) * 256 + threadIdx.x;
        if (i < out_n) out[i] = 0.0f;
    }
}

// ---------------- degree histograms (4 edges/thread) --------------------------
__global__ void k_hist(const int* __restrict__ src, const int* __restrict__ dst, int E) {
    int q = blockIdx.x * blockDim.x + threadIdx.x;
    int e0 = q * 4;
    if (e0 + 3 < E) {
        int4 s = *reinterpret_cast<const int4*>(src + e0);
        int4 d = *reinterpret_cast<const int4*>(dst + e0);
        atomicAdd(&g_cnt_src[s.x], 1); atomicAdd(&g_cnt_src[s.y], 1);
        atomicAdd(&g_cnt_src[s.z], 1); atomicAdd(&g_cnt_src[s.w], 1);
        atomicAdd(&g_cnt_dst[d.x], 1); atomicAdd(&g_cnt_dst[d.y], 1);
        atomicAdd(&g_cnt_dst[d.z], 1); atomicAdd(&g_cnt_dst[d.w], 1);
    } else {
        for (int e = e0; e < E; ++e) {
            atomicAdd(&g_cnt_src[src[e]], 1);
            atomicAdd(&g_cnt_dst[dst[e]], 1);
        }
    }
}

// ---------------- scan of in-degree counts -> row_ptr (+ norm_dst) ------------
__global__ void k_scan1(int n) {
    __shared__ int s[SCAN_B];
    int i = blockIdx.x * SCAN_B + threadIdx.x;
    int v = (i < n) ? g_cnt_dst[i] : 0;
    if (i < n) g_norm_dst[i] = rsqrtf((float)max(v, 1));
    s[threadIdx.x] = v;
    __syncthreads();
    for (int off = 1; off < SCAN_B; off <<= 1) {
        int t = (threadIdx.x >= off) ? s[threadIdx.x - off] : 0;
        __syncthreads();
        s[threadIdx.x] += t;
        __syncthreads();
    }
    if (i < n) g_row_ptr[i] = s[threadIdx.x] - v;
    if (threadIdx.x == SCAN_B - 1) g_spine[blockIdx.x] = s[SCAN_B - 1];
}

__global__ void k_scan2(int nb) {
    __shared__ int s[SCAN_B];
    int v = (threadIdx.x < nb) ? g_spine[threadIdx.x] : 0;
    s[threadIdx.x] = v;
    __syncthreads();
    for (int off = 1; off < SCAN_B; off <<= 1) {
        int t = (threadIdx.x >= off) ? s[threadIdx.x - off] : 0;
        __syncthreads();
        s[threadIdx.x] += t;
        __syncthreads();
    }
    if (threadIdx.x < nb) g_spine[threadIdx.x] = s[threadIdx.x] - v;
}

__global__ void k_scan3(int n, int E) {
    int i = blockIdx.x * blockDim.x + threadIdx.x;
    if (i < n) {
        int r = g_row_ptr[i] + g_spine[i / SCAN_B];
        g_row_ptr[i] = r;
        g_cursor[i]  = r;
    }
    if (i == 0) g_row_ptr[n] = E;
}

// ---------------- CSR fill (counting sort by dst, 4 edges/thread) -------------
__global__ void k_fill(const int* __restrict__ src, const int* __restrict__ dst, int E) {
    int q = blockIdx.x * blockDim.x + threadIdx.x;
    int e0 = q * 4;
    if (e0 + 3 < E) {
        int4 s = *reinterpret_cast<const int4*>(src + e0);
        int4 d = *reinterpret_cast<const int4*>(dst + e0);
        g_csr[atomicAdd(&g_cursor[d.x], 1)] = s.x;
        g_csr[atomicAdd(&g_cursor[d.y], 1)] = s.y;
        g_csr[atomicAdd(&g_cursor[d.z], 1)] = s.z;
        g_csr[atomicAdd(&g_cursor[d.w], 1)] = s.w;
    } else {
        for (int e = e0; e < E; ++e)
            g_csr[atomicAdd(&g_cursor[dst[e]], 1)] = src[e];
    }
}

// ---------------- embedding gather -> fp16 h ---------------------------------
__global__ void k_embed(const int* __restrict__ feat_id, const float* __restrict__ emb, int n) {
    int idx = blockIdx.x * blockDim.x + threadIdx.x;
    if (idx < n * 16) {
        int node = idx >> 4;
        int c    = idx & 15;
        const float4* e = reinterpret_cast<const float4*>(emb) + (size_t)feat_id[node] * 32 + c * 2;
        float4 a = e[0], b = e[1];
        __half2 h0 = __floats2half2_rn(a.x, a.y);
        __half2 h1 = __floats2half2_rn(a.z, a.w);
        __half2 h2 = __floats2half2_rn(b.x, b.y);
        __half2 h3 = __floats2half2_rn(b.z, b.w);
        uint4 v;
        v.x = *reinterpret_cast<uint32_t*>(&h0);
        v.y = *reinterpret_cast<uint32_t*>(&h1);
        v.z = *reinterpret_cast<uint32_t*>(&h2);
        v.w = *reinterpret_cast<uint32_t*>(&h3);
        reinterpret_cast<uint4*>(g_hf)[idx] = v;
    }
}

// ---------------- persistent HMMA GEMM: hw = norm_src ⊙ (h @ W) --------------
#define SMO_B  0
#define SMO_A0 34816
#define SMO_A1 69632
#define SM_GEMM 104448

__global__ void __launch_bounds__(256) k_gemm_hmma(const __half* __restrict__ Wt,
                                                   int n, int tiles) {
    extern __shared__ char sm[];
    uint32_t sBu  = smem_u32(sm) + SMO_B;
    uint32_t sAu[2] = { smem_u32(sm) + SMO_A0, smem_u32(sm) + SMO_A1 };
    int tid = threadIdx.x, warp = tid >> 5, lane = tid & 31;

    int t0 = blockIdx.x;
    if (t0 >= tiles) return;

    const uint4* Asrc = reinterpret_cast<const uint4*>(g_hf);
    const uint4* Bsrc = reinterpret_cast<const uint4*>(Wt);

    for (int i = tid; i < 2048; i += 256) {
        int r = i >> 4, c = i & 15;
        cp16(sBu + r * ASTB + c * 16, Bsrc + i, 16);
    }
    {
        int row0 = t0 * 128;
        for (int i = tid; i < 2048; i += 256) {
            int r = i >> 4, c = i & 15;
            int gr = row0 + r;
            int ok = (gr < n) ? 16 : 0;
            int grc = (gr < n) ? gr : 0;
            cp16(sAu[0] + r * ASTB + c * 16, Asrc + ((size_t)grc * 16 + c), ok);
        }
    }
    cp_commit();
    cp_wait0();
    __syncthreads();

    int wm = warp >> 1, wn = warp & 1;
    int m0 = wm * 32, nn0 = wn * 64;

    uint32_t a_off = (m0 + (lane & 7) + ((lane & 8) ? 8 : 0)) * ASTB
                   + ((lane & 16) ? 16 : 0);
    uint32_t b_base = sBu + (nn0 + (lane & 7) + ((lane & 16) ? 8 : 0)) * ASTB
                          + ((lane & 8) ? 16 : 0);

    int cur = 0;
    for (int t = t0; t < tiles; t += GRIDP) {
        int row0 = t * 128;
        int tnext = t + GRIDP;

        if (tnext < tiles) {
            int nrow0 = tnext * 128;
            for (int i = tid; i < 2048; i += 256) {
                int r = i >> 4, c = i & 15;
                int gr = nrow0 + r;
                int ok = (gr < n) ? 16 : 0;
                int grc = (gr < n) ? gr : 0;
                cp16(sAu[cur ^ 1] + r * ASTB + c * 16, Asrc + ((size_t)grc * 16 + c), ok);
            }
            cp_commit();
        }

        uint32_t a_base = sAu[cur] + a_off;

        float acc[2][8][4];
#pragma unroll
        for (int mt = 0; mt < 2; mt++)
#pragma unroll
            for (int j = 0; j < 8; j++)
#pragma unroll
                for (int q = 0; q < 4; q++) acc[mt][j][q] = 0.f;

#pragma unroll
        for (int ks = 0; ks < 8; ks++) {
            uint32_t a[2][4];
#pragma unroll
            for (int mt = 0; mt < 2; mt++)
                ldsm_x4(a[mt][0], a[mt][1], a[mt][2], a[mt][3],
                        a_base + mt * 16 * ASTB + ks * 32);
#pragma unroll
            for (int jj = 0; jj < 4; jj++) {
                uint32_t b0, b1, b2, b3;
                ldsm_x4(b0, b1, b2, b3, b_base + jj * 16 * ASTB + ks * 32);
#pragma unroll
                for (int mt = 0; mt < 2; mt++) {
                    mma16816(acc[mt][2 * jj],     a[mt][0], a[mt][1], a[mt][2], a[mt][3], b0, b1);
                    mma16816(acc[mt][2 * jj + 1], a[mt][0], a[mt][1], a[mt][2], a[mt][3], b2, b3);
                }
            }
        }
        __syncthreads();

        float ns0[2], ns1[2];
#pragma unroll
        for (int mt = 0; mt < 2; mt++) {
            int mr0 = row0 + m0 + mt * 16 + (lane >> 2);
            int mr1 = mr0 + 8;
            ns0[mt] = (mr0 < n) ? rsqrtf((float)max(g_cnt_src[mr0], 1)) : 0.f;
            ns1[mt] = (mr1 < n) ? rsqrtf((float)max(g_cnt_src[mr1], 1)) : 0.f;
        }
#pragma unroll
        for (int mt = 0; mt < 2; mt++) {
            uint32_t st_base = sAu[cur]
                + (m0 + mt * 16 + (lane & 7) + ((lane & 8) ? 8 : 0)) * ASTB
                + nn0 * 2 + ((lane & 16) ? 16 : 0);
#pragma unroll
            for (int jj = 0; jj < 4; jj++) {
                __half2 t0lo = __floats2half2_rn(acc[mt][2*jj][0] * ns0[mt],
                                                 acc[mt][2*jj][1] * ns0[mt]);
                __half2 t0hi = __floats2half2_rn(acc[mt][2*jj][2] * ns1[mt],
                                                 acc[mt][2*jj][3] * ns1[mt]);
                __half2 t1lo = __floats2half2_rn(acc[mt][2*jj+1][0] * ns0[mt],
                                                 acc[mt][2*jj+1][1] * ns0[mt]);
                __half2 t1hi = __floats2half2_rn(acc[mt][2*jj+1][2] * ns1[mt],
                                                 acc[mt][2*jj+1][3] * ns1[mt]);
                stsm_x4(st_base + jj * 32,
                        *reinterpret_cast<uint32_t*>(&t0lo),
                        *reinterpret_cast<uint32_t*>(&t0hi),
                        *reinterpret_cast<uint32_t*>(&t1lo),
                        *reinterpret_cast<uint32_t*>(&t1hi));
            }
        }
        __syncthreads();

        char* sAc = sm + (cur ? SMO_A1 : SMO_A0);
        for (int i = tid; i < 2048; i += 256) {
            int r = i >> 4, c = i & 15;
            int gr = row0 + r;
            if (gr < n)
                reinterpret_cast<uint4*>(g_hw)[(size_t)gr * 16 + c] =
                    *reinterpret_cast<uint4*>(sAc + r * ASTB + c * 16);
        }

        if (tnext < tiles) {
            cp_wait0();
            __syncthreads();
        }
        cur ^= 1;
    }
}

// ---------------- edge aggregation (intermediate layers) ----------------------
// half-warp per dst node; lane owns 8 dims (16B fp16 LDG.128), unroll 8.
__global__ void __launch_bounds__(256) k_agg(const float* __restrict__ bias, int n) {
    int gw   = (blockIdx.x * blockDim.x + threadIdx.x) >> 5;
    int lane = threadIdx.x & 31;
    int node = gw * 2 + (lane >> 4);
    int l16  = lane & 15;
    if (node >= n) return;

    int beg = g_row_ptr[node];
    int end = g_row_ptr[node + 1];

    const uint4* hw4 = reinterpret_cast<const uint4*>(g_hw);
    float a0 = 0.f, a1 = 0.f, a2 = 0.f, a3 = 0.f;
    float a4 = 0.f, a5 = 0.f, a6 = 0.f, a7 = 0.f;

    int e = beg;
    for (; e + 7 < end; e += 8) {
        int s[8];
#pragma unroll
        for (int j = 0; j < 8; j++) s[j] = g_csr[e + j];
        uint4 v[8];
#pragma unroll
        for (int j = 0; j < 8; j++) v[j] = hw4[(size_t)s[j] * 16 + l16];
#pragma unroll
        for (int j = 0; j < 8; j++) {
            float2 f0 = __half22float2(*reinterpret_cast<__half2*>(&v[j].x));
            float2 f1 = __half22float2(*reinterpret_cast<__half2*>(&v[j].y));
            float2 f2 = __half22float2(*reinterpret_cast<__half2*>(&v[j].z));
            float2 f3 = __half22float2(*reinterpret_cast<__half2*>(&v[j].w));
            a0 += f0.x; a1 += f0.y; a2 += f1.x; a3 += f1.y;
            a4 += f2.x; a5 += f2.y; a6 += f3.x; a7 += f3.y;
        }
    }
    for (; e < end; ++e) {
        uint4 v = hw4[(size_t)g_csr[e] * 16 + l16];
        float2 f0 = __half22float2(*reinterpret_cast<__half2*>(&v.x));
        float2 f1 = __half22float2(*reinterpret_cast<__half2*>(&v.y));
        float2 f2 = __half22float2(*reinterpret_cast<__half2*>(&v.z));
        float2 f3 = __half22float2(*reinterpret_cast<__half2*>(&v.w));
        a0 += f0.x; a1 += f0.y; a2 += f1.x; a3 += f1.y;
        a4 += f2.x; a5 += f2.y; a6 += f3.x; a7 += f3.y;
    }

    float nd = g_norm_dst[node];
    float4 bb0 = reinterpret_cast<const float4*>(bias)[l16 * 2];
    float4 bb1 = reinterpret_cast<const float4*>(bias)[l16 * 2 + 1];
    __half2 p0 = __floats2half2_rn(fmaxf(fmaf(a0, nd, bb0.x), 0.f),
                                   fmaxf(fmaf(a1, nd, bb0.y), 0.f));
    __half2 p1 = __floats2half2_rn(fmaxf(fmaf(a2, nd, bb0.z), 0.f),
                                   fmaxf(fmaf(a3, nd, bb0.w), 0.f));
    __half2 p2 = __floats2half2_rn(fmaxf(fmaf(a4, nd, bb1.x), 0.f),
                                   fmaxf(fmaf(a5, nd, bb1.y), 0.f));
    __half2 p3 = __floats2half2_rn(fmaxf(fmaf(a6, nd, bb1.z), 0.f),
                                   fmaxf(fmaf(a7, nd, bb1.w), 0.f));
    uint4 o;
    o.x = *reinterpret_cast<uint32_t*>(&p0);
    o.y = *reinterpret_cast<uint32_t*>(&p1);
    o.z = *reinterpret_cast<uint32_t*>(&p2);
    o.w = *reinterpret_cast<uint32_t*>(&p3);
    reinterpret_cast<uint4*>(g_hf)[(size_t)node * 16 + l16] = o;
}

// ---------------- fused final agg + per-graph max readout --------------------
// Block handles 64 consecutive nodes (4 waves x 16 half-warp teams).
// Node aggregates stay in regs (fp32, never quantized), max-reduced into smem
// per-graph slots (int-compare valid: relu >= 0, out zeroed), flushed once.
__global__ void __launch_bounds__(256) k_agg_rd(const float* __restrict__ bias,
                                                const int* __restrict__ gids,
                                                float* __restrict__ out, int n) {
    __shared__ int smax[RD_SLOTS * DIMV];
    __shared__ int s_g0;
    int tid = threadIdx.x;
    int n0 = blockIdx.x * 64;
    if (n0 >= n) return;

    for (int i = tid; i < RD_SLOTS * DIMV; i += 256) smax[i] = 0;
    if (tid == 0) s_g0 = gids[n0];
    __syncthreads();
    int g0 = s_g0;

    int l16 = tid & 15;
    int team = tid >> 4;   // 0..15
    const uint4* hw4 = reinterpret_cast<const uint4*>(g_hw);
    float4 bb0 = reinterpret_cast<const float4*>(bias)[l16 * 2];
    float4 bb1 = reinterpret_cast<const float4*>(bias)[l16 * 2 + 1];

    for (int wave = 0; wave < 4; wave++) {
        int node = n0 + wave * 16 + team;
        if (node < n) {
            int beg = g_row_ptr[node];
            int end = g_row_ptr[node + 1];
            float a0 = 0.f, a1 = 0.f, a2 = 0.f, a3 = 0.f;
            float a4 = 0.f, a5 = 0.f, a6 = 0.f, a7 = 0.f;
            int e = beg;
            for (; e + 7 < end; e += 8) {
                int s[8];
#pragma unroll
                for (int j = 0; j < 8; j++) s[j] = g_csr[e + j];
                uint4 v[8];
#pragma unroll
                for (int j = 0; j < 8; j++) v[j] = hw4[(size_t)s[j] * 16 + l16];
#pragma unroll
                for (int j = 0; j < 8; j++) {
                    float2 f0 = __half22float2(*reinterpret_cast<__half2*>(&v[j].x));
                    float2 f1 = __half22float2(*reinterpret_cast<__half2*>(&v[j].y));
                    float2 f2 = __half22float2(*reinterpret_cast<__half2*>(&v[j].z));
                    float2 f3 = __half22float2(*reinterpret_cast<__half2*>(&v[j].w));
                    a0 += f0.x; a1 += f0.y; a2 += f1.x; a3 += f1.y;
                    a4 += f2.x; a5 += f2.y; a6 += f3.x; a7 += f3.y;
                }
            }
            for (; e < end; ++e) {
                uint4 v = hw4[(size_t)g_csr[e] * 16 + l16];
                float2 f0 = __half22float2(*reinterpret_cast<__half2*>(&v.x));
                float2 f1 = __half22float2(*reinterpret_cast<__half2*>(&v.y));
                float2 f2 = __half22float2(*reinterpret_cast<__half2*>(&v.z));
                float2 f3 = __half22float2(*reinterpret_cast<__half2*>(&v.w));
                a0 += f0.x; a1 += f0.y; a2 += f1.x; a3 += f1.y;
                a4 += f2.x; a5 += f2.y; a6 += f3.x; a7 += f3.y;
            }

            float nd = g_norm_dst[node];
            float o[8];
            o[0] = fmaxf(fmaf(a0, nd, bb0.x), 0.f);
            o[1] = fmaxf(fmaf(a1, nd, bb0.y), 0.f);
            o[2] = fmaxf(fmaf(a2, nd, bb0.z), 0.f);
            o[3] = fmaxf(fmaf(a3, nd, bb0.w), 0.f);
            o[4] = fmaxf(fmaf(a4, nd, bb1.x), 0.f);
            o[5] = fmaxf(fmaf(a5, nd, bb1.y), 0.f);
            o[6] = fmaxf(fmaf(a6, nd, bb1.z), 0.f);
            o[7] = fmaxf(fmaf(a7, nd, bb1.w), 0.f);

            int g = gids[node];
            int slot = g - g0;
            if (slot < RD_SLOTS) {
                int base = slot * DIMV + l16 * 8;
#pragma unroll
                for (int k = 0; k < 8; k++)
                    atomicMax(&smax[base + k], __float_as_int(o[k]));
            } else {
                // ultra-rare fallback: direct global max
#pragma unroll
                for (int k = 0; k < 8; k++)
                    atomicMax(reinterpret_cast<int*>(&out[(size_t)g * DIMV + l16 * 8 + k]),
                              __float_as_int(o[k]));
            }
        }
    }
    __syncthreads();

    for (int i = tid; i < RD_SLOTS * DIMV; i += 256) {
        int v = smax[i];
        if (v != 0) {
            int slot = i >> 7, dim = i & 127;
            atomicMax(reinterpret_cast<int*>(&out[(size_t)(g0 + slot) * DIMV + dim]), v);
        }
    }
}

// ---------------- launch ------------------------------------------------------
extern "C" void kernel_launch(void* const* d_in, const int* in_sizes, int n_in,
                              void* d_out, int out_size) {
    const int*   feat_id = (const int*)  d_in[0];
    const int*   src     = (const int*)  d_in[1];
    const int*   dst     = (const int*)  d_in[2];
    const int*   gids    = (const int*)  d_in[3];
    const float* emb     = (const float*)d_in[4];
    const float* W       = (const float*)d_in[5];
    const float* b       = (const float*)d_in[6];
    float*       out     = (float*)d_out;

    int N = in_sizes[0];
    int E = in_sizes[1];
    int LAYERS = in_sizes[6] / DIMV;

    const int T = 256;
    int nbN   = (N + T - 1) / T;
    int nbE4  = ((E + 3) / 4 + T - 1) / T;
    int nbSc  = (N + SCAN_B - 1) / SCAN_B;
    int nbOut = (out_size + T - 1) / T;

    cudaFuncSetAttribute(k_gemm_hmma, cudaFuncAttributeMaxDynamicSharedMemorySize, SM_GEMM);

    int tiles = (N + 127) / 128;
    int gemmGrid = (tiles < GRIDP) ? tiles : GRIDP;
    int aggBlocks = ((N + 1) / 2 + 7) / 8;   // 8 warps/block, 2 nodes/warp

    __half* wt_dev = nullptr;
    cudaGetSymbolAddress((void**)&wt_dev, g_wt);

    // --- main stream (0): prep -> embed -> gemm chain
    // --- side stream   : CSR build (hist -> scans -> fill), forked after prep
    k_prep<<<nbN + LAYERS + nbOut, T>>>(W, nbN, N, LAYERS, out, out_size);
    cudaEventRecord(g_si.evA, 0);
    cudaStreamWaitEvent(g_si.s2, g_si.evA, 0);

    k_hist<<<nbE4, T, 0, g_si.s2>>>(src, dst, E);
    cudaEventRecord(g_si.evB, g_si.s2);           // cnt_src/cnt_dst ready
    k_scan1<<<nbSc, SCAN_B, 0, g_si.s2>>>(N);
    k_scan2<<<1, SCAN_B, 0, g_si.s2>>>(nbSc);
    k_scan3<<<nbN, T, 0, g_si.s2>>>(N, E);
    k_fill<<<nbE4, T, 0, g_si.s2>>>(src, dst, E);
    cudaEventRecord(g_si.evC, g_si.s2);           // CSR ready

    k_embed<<<(N * 16 + T - 1) / T, T>>>(feat_id, emb, N);
    cudaStreamWaitEvent(0, g_si.evB, 0);          // gemm epilogue needs cnt_src
    k_gemm_hmma<<<gemmGrid, 256, SM_GEMM>>>(wt_dev, N, tiles);
    cudaStreamWaitEvent(0, g_si.evC, 0);          // agg needs CSR

    for (int l = 0; l < LAYERS; l++) {
        if (l > 0)
            k_gemm_hmma<<<gemmGrid, 256, SM_GEMM>>>(wt_dev + (size_t)l * DIMV * DIMV, N, tiles);
        if (l < LAYERS - 1)
            k_agg<<<aggBlocks, 256>>>(b + (size_t)l * DIMV, N);
        else
            k_agg_rd<<<(N + 63) / 64, 256>>>(b + (size_t)l * DIMV, gids, out, N);
    }
}